// round 2
// baseline (speedup 1.0000x reference)
#include <cuda_runtime.h>
#include <math.h>

// ---- problem constants ----
#define BX   2
#define CDIM 384
#define NHD  12
#define NGRP 6
#define CGRP 64
#define HCH  32
#define LDIM 1024
#define NSD  1024
#define HIDD 1536
#define EPSLN 1e-5f

// ---- scratch ----
__device__ float g_xn [BX*LDIM*CDIM];
__device__ float g_q  [BX*LDIM*CDIM];
__device__ float g_pos[BX*NGRP*NSD*2];
__device__ float g_xs [BX*NSD*CDIM];
__device__ float g_kt [BX*CDIM*NSD];
__device__ float g_vt [BX*CDIM*NSD];
__device__ float g_ao [BX*LDIM*CDIM];
__device__ float g_x2 [BX*LDIM*CDIM];
__device__ float g_ln2[BX*LDIM*CDIM];
__device__ float g_h1 [BX*LDIM*HIDD];

// packed dual-FMA (sm_103a): d = a*b + c elementwise on float2
__device__ __forceinline__ float2 ffma2(float2 a, float2 b, float2 c) {
    float2 d;
    asm("{\n\t"
        ".reg .b64 ra, rb, rc, rd;\n\t"
        "mov.b64 ra, {%2, %3};\n\t"
        "mov.b64 rb, {%4, %5};\n\t"
        "mov.b64 rc, {%6, %7};\n\t"
        "fma.rn.f32x2 rd, ra, rb, rc;\n\t"
        "mov.b64 {%0, %1}, rd;\n\t"
        "}"
        : "=f"(d.x), "=f"(d.y)
        : "f"(a.x), "f"(a.y), "f"(b.x), "f"(b.y), "f"(c.x), "f"(c.y));
    return d;
}

// =============================== LayerNorm ===============================
__global__ void ln_kernel(const float* __restrict__ x, const float* __restrict__ w,
                          const float* __restrict__ b, float* __restrict__ out)
{
    int row = blockIdx.x;
    int t   = threadIdx.x;         // 128
    const float* xr = x + row * CDIM;
    float v0 = xr[t], v1 = xr[t + 128], v2 = xr[t + 256];
    float s  = v0 + v1 + v2;
    float sq = v0*v0 + v1*v1 + v2*v2;
    __shared__ float sh[8];
    #pragma unroll
    for (int o = 16; o; o >>= 1) {
        s  += __shfl_down_sync(0xffffffffu, s,  o);
        sq += __shfl_down_sync(0xffffffffu, sq, o);
    }
    if ((t & 31) == 0) { sh[t >> 5] = s; sh[4 + (t >> 5)] = sq; }
    __syncthreads();
    __shared__ float s_mu, s_rstd;
    if (t == 0) {
        float S = sh[0] + sh[1] + sh[2] + sh[3];
        float SQ = sh[4] + sh[5] + sh[6] + sh[7];
        float mu = S / CDIM;
        s_mu = mu;
        s_rstd = rsqrtf(SQ / CDIM - mu * mu + EPSLN);
    }
    __syncthreads();
    float mu = s_mu, rstd = s_rstd;
    float* orow = out + row * CDIM;
    orow[t]       = (v0 - mu) * rstd * w[t]       + b[t];
    orow[t + 128] = (v1 - mu) * rstd * w[t + 128] + b[t + 128];
    orow[t + 256] = (v2 - mu) * rstd * w[t + 256] + b[t + 256];
}

// =============================== GEMM (f32x2) ===============================
// C[M,N] = A[M,K] @ W[N,K]^T + bias[N]; EPI: 0=none 1=gelu 2=+res; TRANSOUT: (B,C,ns)
template<int EPI, bool TRANSOUT>
__global__ void gemm_kernel(const float* __restrict__ A, const float* __restrict__ W,
                            const float* __restrict__ bias, const float* __restrict__ res,
                            float* __restrict__ out, int M, int N, int K)
{
    __shared__ float As[16][128];   // m-values duplicated in pairs
    __shared__ float Bs[16][64];
    int tid = threadIdx.x;               // 256
    int m0 = blockIdx.y * 64, n0 = blockIdx.x * 64;
    int lr = tid >> 2;                   // 0..63
    int lc = (tid & 3) * 4;              // 0,4,8,12
    const float* Ab = A + (size_t)(m0 + lr) * K + lc;
    const float* Wb = W + (size_t)(n0 + lr) * K + lc;
    int tx = tid & 15, ty = tid >> 4;
    float2 acc[4][2];
    #pragma unroll
    for (int i = 0; i < 4; i++) { acc[i][0] = make_float2(0.f,0.f); acc[i][1] = make_float2(0.f,0.f); }

    for (int k0 = 0; k0 < K; k0 += 16) {
        float4 av = *(const float4*)(Ab + k0);
        float4 wv = *(const float4*)(Wb + k0);
        *(float2*)&As[lc + 0][2*lr] = make_float2(av.x, av.x);
        *(float2*)&As[lc + 1][2*lr] = make_float2(av.y, av.y);
        *(float2*)&As[lc + 2][2*lr] = make_float2(av.z, av.z);
        *(float2*)&As[lc + 3][2*lr] = make_float2(av.w, av.w);
        Bs[lc + 0][lr] = wv.x; Bs[lc + 1][lr] = wv.y;
        Bs[lc + 2][lr] = wv.z; Bs[lc + 3][lr] = wv.w;
        __syncthreads();
        #pragma unroll
        for (int kk = 0; kk < 16; kk++) {
            float4 aA = *(const float4*)&As[kk][ty * 8];
            float4 aB = *(const float4*)&As[kk][ty * 8 + 4];
            float4 b4 = *(const float4*)&Bs[kk][tx * 4];
            float2 b01 = make_float2(b4.x, b4.y);
            float2 b23 = make_float2(b4.z, b4.w);
            float2 aa0 = make_float2(aA.x, aA.y);
            float2 aa1 = make_float2(aA.z, aA.w);
            float2 aa2 = make_float2(aB.x, aB.y);
            float2 aa3 = make_float2(aB.z, aB.w);
            acc[0][0] = ffma2(aa0, b01, acc[0][0]); acc[0][1] = ffma2(aa0, b23, acc[0][1]);
            acc[1][0] = ffma2(aa1, b01, acc[1][0]); acc[1][1] = ffma2(aa1, b23, acc[1][1]);
            acc[2][0] = ffma2(aa2, b01, acc[2][0]); acc[2][1] = ffma2(aa2, b23, acc[2][1]);
            acc[3][0] = ffma2(aa3, b01, acc[3][0]); acc[3][1] = ffma2(aa3, b23, acc[3][1]);
        }
        __syncthreads();
    }

    float accs[4][4];
    #pragma unroll
    for (int i = 0; i < 4; i++) {
        accs[i][0] = acc[i][0].x; accs[i][1] = acc[i][0].y;
        accs[i][2] = acc[i][1].x; accs[i][3] = acc[i][1].y;
    }
    #pragma unroll
    for (int j = 0; j < 4; j++) {
        int n = n0 + tx * 4 + j;
        float bj = bias[n];
        #pragma unroll
        for (int i = 0; i < 4; i++) {
            int m = m0 + ty * 4 + i;
            float c = accs[i][j] + bj;
            if (EPI == 1) c = 0.5f * c * (1.0f + erff(c * 0.70710678118654752f));
            if (EPI == 2) c += res[(size_t)m * N + n];
            if (TRANSOUT) out[(size_t)(m >> 10) * N * 1024 + (size_t)n * 1024 + (m & 1023)] = c;
            else          out[(size_t)m * N + n] = c;
        }
    }
}

// ========================= Offset network (fused) =========================
__global__ void offset_kernel(const float* __restrict__ q, const float* __restrict__ dww,
                              const float* __restrict__ dwb, const float* __restrict__ lnw,
                              const float* __restrict__ lnb, const float* __restrict__ pww,
                              float* __restrict__ pos)
{
    int pix = blockIdx.x;
    int c = threadIdx.x;               // 64
    int bg = pix >> 10;
    int l  = pix & 1023;
    int y = l >> 5, x = l & 31;
    int b = bg / NGRP, g = bg % NGRP;
    int ch = g * CGRP + c;
    const float* w = dww + c * 49;
    float acc = dwb[c];
    #pragma unroll
    for (int dy = -3; dy <= 3; ++dy) {
        int yy = y + dy;
        if ((unsigned)yy >= 32u) continue;
        #pragma unroll
        for (int dx = -3; dx <= 3; ++dx) {
            int xx = x + dx;
            if ((unsigned)xx >= 32u) continue;
            acc += q[(size_t)(b * LDIM + yy * 32 + xx) * CDIM + ch] * w[(dy + 3) * 7 + (dx + 3)];
        }
    }
    float s = acc, sq = acc * acc;
    #pragma unroll
    for (int o = 16; o; o >>= 1) {
        s  += __shfl_down_sync(0xffffffffu, s,  o);
        sq += __shfl_down_sync(0xffffffffu, sq, o);
    }
    __shared__ float sh[4];
    if ((c & 31) == 0) { sh[c >> 5] = s; sh[2 + (c >> 5)] = sq; }
    __syncthreads();
    float mu  = (sh[0] + sh[1]) * (1.0f / 64.0f);
    float var = (sh[2] + sh[3]) * (1.0f / 64.0f) - mu * mu;
    float r = rsqrtf(var + EPSLN);
    float o_ = (acc - mu) * r * lnw[c] + lnb[c];
    o_ = 0.5f * o_ * (1.0f + erff(o_ * 0.70710678118654752f));
    float p0 = o_ * pww[c];
    float p1 = o_ * pww[64 + c];
    #pragma unroll
    for (int o = 16; o; o >>= 1) {
        p0 += __shfl_down_sync(0xffffffffu, p0, o);
        p1 += __shfl_down_sync(0xffffffffu, p1, o);
    }
    __shared__ float ph[4];
    if ((c & 31) == 0) { ph[c >> 5] = p0; ph[2 + (c >> 5)] = p1; }
    __syncthreads();
    if (c == 0) {
        float P0 = ph[0] + ph[1];
        float P1 = ph[2] + ph[3];
        float oy = tanhf(P0) * (2.0f / 32.0f);
        float ox = tanhf(P1) * (2.0f / 32.0f);
        float py = oy + ((y + 0.5f) / 32.0f) * 2.0f - 1.0f;
        float px = ox + ((x + 0.5f) / 32.0f) * 2.0f - 1.0f;
        pos[(size_t)bg * 2048 + l * 2 + 0] = py;
        pos[(size_t)bg * 2048 + l * 2 + 1] = px;
    }
}

// ===================== Deformable bilinear sampling =====================
__global__ void sample_kernel(const float* __restrict__ xn, const float* __restrict__ pos,
                              float* __restrict__ xs)
{
    int bn = blockIdx.x;
    int c = threadIdx.x;               // 384
    int b = bn >> 10;
    int n = bn & 1023;
    int g = c >> 6;
    float py = pos[(size_t)(b * NGRP + g) * 2048 + n * 2 + 0];
    float px = pos[(size_t)(b * NGRP + g) * 2048 + n * 2 + 1];
    float fx = (px + 1.0f) * 0.5f * 31.0f;
    float fy = (py + 1.0f) * 0.5f * 31.0f;
    float x0f = floorf(fx), y0f = floorf(fy);
    int x0 = (int)x0f, y0 = (int)y0f;
    float wx = fx - x0f, wy = fy - y0f;
    const float* base = xn + (size_t)b * LDIM * CDIM + c;
    float v = 0.0f;
    if ((unsigned)x0 < 32u && (unsigned)y0 < 32u)
        v += (1 - wx) * (1 - wy) * base[(size_t)(y0 * 32 + x0) * CDIM];
    if ((unsigned)(x0 + 1) < 32u && (unsigned)y0 < 32u)
        v += wx * (1 - wy) * base[(size_t)(y0 * 32 + x0 + 1) * CDIM];
    if ((unsigned)x0 < 32u && (unsigned)(y0 + 1) < 32u)
        v += (1 - wx) * wy * base[(size_t)((y0 + 1) * 32 + x0) * CDIM];
    if ((unsigned)(x0 + 1) < 32u && (unsigned)(y0 + 1) < 32u)
        v += wx * wy * base[(size_t)((y0 + 1) * 32 + x0 + 1) * CDIM];
    xs[(size_t)bn * CDIM + c] = v;
}

// ========== Tiled attention: 32 queries/block, 2-pass, big smem ==========
// grid (32 qtiles, 12 heads, 2 batch), 256 threads, ~168KB dynamic smem
#define ATTN_SMEM_FLOATS (32*1024 + 2048 + 2048 + 2048 + 3972 + 64)
__global__ void attn2_kernel(const float* __restrict__ q, const float* __restrict__ kt,
                             const float* __restrict__ vt, const float* __restrict__ pos,
                             const float* __restrict__ rpe, float* __restrict__ ao)
{
    extern __shared__ float sm[];
    float* s_logit = sm;                    // 32*1024
    float* s_pos   = sm + 32768;            // 2048
    float* s_k     = s_pos + 2048;          // 32 x 64
    float* s_qd    = s_k + 2048;            // 32 x 64  (q duplicated pairs)
    float* s_rpe   = s_qd + 2048;           // 3969 (pad 3972)
    float* s_max   = s_rpe + 3972;          // 32
    float* s_sum   = s_max + 32;            // 32

    int m0 = blockIdx.x * 32;
    int hh = blockIdx.y;
    int b  = blockIdx.z;
    int g  = hh >> 1;
    int t  = threadIdx.x;                   // 256

    for (int i = t; i < 3969; i += 256) s_rpe[i] = rpe[hh * 3969 + i];
    {
        const float* posb = pos + (size_t)(b * NGRP + g) * 2048;
        for (int i = t; i < 2048; i += 256) s_pos[i] = posb[i];
    }
    for (int i = t; i < 1024; i += 256) {
        int qq = i >> 5, d = i & 31;
        float v = q[(size_t)(b * LDIM + m0 + qq) * CDIM + hh * HCH + d];
        s_qd[d * 64 + 2 * qq]     = v;
        s_qd[d * 64 + 2 * qq + 1] = v;
    }

    int qg = t >> 4;          // 0..15 -> q pair base
    int ng = t & 15;          // 0..15 -> n group of 4
    int q0 = qg * 2, q1 = q0 + 1;
    int mg0 = m0 + q0, mg1 = m0 + q1;
    float qgy0 = ((float)(mg0 >> 5) + 0.5f) * (1.0f / 16.0f) - 1.0f;
    float qgx0 = ((float)(mg0 & 31) + 0.5f) * (1.0f / 16.0f) - 1.0f;
    float qgy1 = ((float)(mg1 >> 5) + 0.5f) * (1.0f / 16.0f) - 1.0f;
    float qgx1 = ((float)(mg1 & 31) + 0.5f) * (1.0f / 16.0f) - 1.0f;

    const float* ktb = kt + (size_t)b * CDIM * NSD + (size_t)hh * HCH * NSD;
    const float scale = 0.17677669529663687f;  // 1/sqrt(32)
    float mrun0 = -1e30f, mrun1 = -1e30f;

    for (int nc = 0; nc < 1024; nc += 64) {
        __syncthreads();
        #pragma unroll
        for (int i = 0; i < 8; i++) {
            int idx = t + i * 256;
            int d = idx >> 6, n = idx & 63;
            s_k[idx] = ktb[(size_t)d * 1024 + nc + n];
        }
        __syncthreads();

        float2 a00 = make_float2(0.f,0.f), a01 = make_float2(0.f,0.f);
        float2 a10 = make_float2(0.f,0.f), a11 = make_float2(0.f,0.f);
        #pragma unroll
        for (int d = 0; d < 32; d++) {
            float4 qk  = *(const float4*)&s_qd[d * 64 + qg * 4];
            float4 kk4 = *(const float4*)&s_k [d * 64 + ng * 4];
            float2 k01 = make_float2(kk4.x, kk4.y);
            float2 k23 = make_float2(kk4.z, kk4.w);
            float2 aa0 = make_float2(qk.x, qk.y);
            float2 aa1 = make_float2(qk.z, qk.w);
            a00 = ffma2(aa0, k01, a00);
            a01 = ffma2(aa0, k23, a01);
            a10 = ffma2(aa1, k01, a10);
            a11 = ffma2(aa1, k23, a11);
        }
        float sv[2][4] = {{a00.x, a00.y, a01.x, a01.y},
                          {a10.x, a10.y, a11.x, a11.y}};
        #pragma unroll
        for (int qq = 0; qq < 2; qq++) {
            float qgy = qq ? qgy1 : qgy0;
            float qgx = qq ? qgx1 : qgx0;
            int qrow = qq ? q1 : q0;
            #pragma unroll
            for (int nn = 0; nn < 4; nn++) {
                int n = nc + ng * 4 + nn;
                float py = s_pos[2 * n], px = s_pos[2 * n + 1];
                float fy = ((qgy - py) * 0.5f + 1.0f) * 31.0f;
                float fx = ((qgx - px) * 0.5f + 1.0f) * 31.0f;
                float x0f = floorf(fx), y0f = floorf(fy);
                int xi = (int)x0f, yi = (int)y0f;
                float wx = fx - x0f, wy = fy - y0f;
                float bias = 0.0f;
                if ((unsigned)xi < 63u && (unsigned)yi < 63u)             bias += (1 - wx) * (1 - wy) * s_rpe[yi * 63 + xi];
                if ((unsigned)(xi + 1) < 63u && (unsigned)yi < 63u)       bias += wx * (1 - wy) * s_rpe[yi * 63 + xi + 1];
                if ((unsigned)xi < 63u && (unsigned)(yi + 1) < 63u)       bias += (1 - wx) * wy * s_rpe[(yi + 1) * 63 + xi];
                if ((unsigned)(xi + 1) < 63u && (unsigned)(yi + 1) < 63u) bias += wx * wy * s_rpe[(yi + 1) * 63 + xi + 1];
                float val = sv[qq][nn] * scale + bias;
                s_logit[qrow * 1024 + n] = val;
                if (qq == 0) mrun0 = fmaxf(mrun0, val);
                else         mrun1 = fmaxf(mrun1, val);
            }
        }
    }

    // per-q max over the 16 n-threads
    #pragma unroll
    for (int o = 8; o; o >>= 1) {
        mrun0 = fmaxf(mrun0, __shfl_xor_sync(0xffffffffu, mrun0, o));
        mrun1 = fmaxf(mrun1, __shfl_xor_sync(0xffffffffu, mrun1, o));
    }
    if (ng == 0) { s_max[q0] = mrun0; s_max[q1] = mrun1; }
    __syncthreads();

    // exp + sum: warp per 4 q rows
    int w = t >> 5, lane = t & 31;
    #pragma unroll
    for (int qq = 0; qq < 4; qq++) {
        int qr = w * 4 + qq;
        float mx = s_max[qr];
        float* Lr = s_logit + qr * 1024;
        float sum = 0.0f;
        #pragma unroll 8
        for (int i = lane; i < 1024; i += 32) {
            float e = __expf(Lr[i] - mx);
            Lr[i] = e;
            sum += e;
        }
        #pragma unroll
        for (int o = 16; o; o >>= 1) sum += __shfl_xor_sync(0xffffffffu, sum, o);
        if (lane == 0) s_sum[qr] = 1.0f / sum;
    }
    __syncthreads();

    // AV: warp w handles d in {w, w+8, w+16, w+24}
    const float* vtb = vt + (size_t)b * CDIM * NSD + (size_t)hh * HCH * NSD;
    #pragma unroll
    for (int dd = 0; dd < 4; dd++) {
        int d = w + dd * 8;
        const float* vr = vtb + (size_t)d * 1024;
        float2 v2[16];
        #pragma unroll
        for (int i = 0; i < 16; i++) v2[i] = *(const float2*)&vr[lane * 2 + i * 64];
        for (int qr = 0; qr < 32; qr++) {
            const float* Lr = s_logit + qr * 1024;
            float2 acc = make_float2(0.f, 0.f);
            #pragma unroll
            for (int i = 0; i < 16; i++) {
                float2 p2 = *(const float2*)&Lr[lane * 2 + i * 64];
                acc = ffma2(p2, v2[i], acc);
            }
            float a = acc.x + acc.y;
            #pragma unroll
            for (int o = 16; o; o >>= 1) a += __shfl_xor_sync(0xffffffffu, a, o);
            if (lane == 0)
                ao[(size_t)(b * LDIM + m0 + qr) * CDIM + hh * HCH + d] = a * s_sum[qr];
        }
    }
}

// =============================== host ===============================
extern "C" void kernel_launch(void* const* d_in, const int* in_sizes, int n_in,
                              void* d_out, int out_size)
{
    const float* x     = (const float*)d_in[0];
    const float* n1w   = (const float*)d_in[1];
    const float* n1b   = (const float*)d_in[2];
    const float* wq    = (const float*)d_in[3];
    const float* bq    = (const float*)d_in[4];
    const float* wk    = (const float*)d_in[5];
    const float* bk    = (const float*)d_in[6];
    const float* wv    = (const float*)d_in[7];
    const float* bv    = (const float*)d_in[8];
    const float* wo    = (const float*)d_in[9];
    const float* bo    = (const float*)d_in[10];
    const float* dww   = (const float*)d_in[11];
    const float* dwb   = (const float*)d_in[12];
    const float* lnw   = (const float*)d_in[13];
    const float* lnb   = (const float*)d_in[14];
    const float* pww   = (const float*)d_in[15];
    const float* rpe   = (const float*)d_in[16];
    const float* n2w   = (const float*)d_in[17];
    const float* n2b   = (const float*)d_in[18];
    const float* fc1w  = (const float*)d_in[19];
    const float* fc1b  = (const float*)d_in[20];
    const float* fc2w  = (const float*)d_in[21];
    const float* fc2b  = (const float*)d_in[22];
    float* out = (float*)d_out;

    float *p_xn, *p_q, *p_pos, *p_xs, *p_kt, *p_vt, *p_ao, *p_x2, *p_ln2, *p_h1;
    cudaGetSymbolAddress((void**)&p_xn,  g_xn);
    cudaGetSymbolAddress((void**)&p_q,   g_q);
    cudaGetSymbolAddress((void**)&p_pos, g_pos);
    cudaGetSymbolAddress((void**)&p_xs,  g_xs);
    cudaGetSymbolAddress((void**)&p_kt,  g_kt);
    cudaGetSymbolAddress((void**)&p_vt,  g_vt);
    cudaGetSymbolAddress((void**)&p_ao,  g_ao);
    cudaGetSymbolAddress((void**)&p_x2,  g_x2);
    cudaGetSymbolAddress((void**)&p_ln2, g_ln2);
    cudaGetSymbolAddress((void**)&p_h1,  g_h1);

    const int M = BX * LDIM;   // 2048
    const int attn_smem = ATTN_SMEM_FLOATS * (int)sizeof(float);
    cudaFuncSetAttribute(attn2_kernel, cudaFuncAttributeMaxDynamicSharedMemorySize, attn_smem);

    ln_kernel<<<M, 128>>>(x, n1w, n1b, p_xn);
    gemm_kernel<0, false><<<dim3(CDIM / 64, M / 64), 256>>>(p_xn, wq, bq, nullptr, p_q, M, CDIM, CDIM);
    offset_kernel<<<BX * NGRP * 1024, 64>>>(p_q, dww, dwb, lnw, lnb, pww, p_pos);
    sample_kernel<<<BX * NSD, CDIM>>>(p_xn, p_pos, p_xs);
    gemm_kernel<0, true><<<dim3(CDIM / 64, M / 64), 256>>>(p_xs, wk, bk, nullptr, p_kt, M, CDIM, CDIM);
    gemm_kernel<0, true><<<dim3(CDIM / 64, M / 64), 256>>>(p_xs, wv, bv, nullptr, p_vt, M, CDIM, CDIM);
    attn2_kernel<<<dim3(32, NHD, BX), 256, attn_smem>>>(p_q, p_kt, p_vt, p_pos, rpe, p_ao);
    gemm_kernel<2, false><<<dim3(CDIM / 64, M / 64), 256>>>(p_ao, wo, bo, x, p_x2, M, CDIM, CDIM);
    ln_kernel<<<M, 128>>>(p_x2, n2w, n2b, p_ln2);
    gemm_kernel<1, false><<<dim3(HIDD / 64, M / 64), 256>>>(p_ln2, fc1w, fc1b, nullptr, p_h1, M, HIDD, CDIM);
    gemm_kernel<2, false><<<dim3(CDIM / 64, M / 64), 256>>>(p_h1, fc2w, fc2b, p_x2, out, M, CDIM, HIDD);
}

// round 3
// speedup vs baseline: 1.1956x; 1.1956x over previous
#include <cuda_runtime.h>
#include <math.h>

// ---- problem constants ----
#define BX   2
#define CDIM 384
#define NHD  12
#define NGRP 6
#define CGRP 64
#define HCH  32
#define LDIM 1024
#define NSD  1024
#define HIDD 1536
#define EPSLN 1e-5f

// ---- scratch ----
__device__ float g_xn [BX*LDIM*CDIM];
__device__ float g_q  [BX*LDIM*CDIM];
__device__ float g_pos[BX*NGRP*NSD*2];
__device__ float g_xs [BX*NSD*CDIM];
__device__ float g_kt [BX*CDIM*NSD];
__device__ float g_vt [BX*CDIM*NSD];
__device__ float g_ao [BX*LDIM*CDIM];
__device__ float g_x2 [BX*LDIM*CDIM];
__device__ float g_ln2[BX*LDIM*CDIM];
__device__ float g_h1 [BX*LDIM*HIDD];

// =============================== LayerNorm ===============================
__global__ void ln_kernel(const float* __restrict__ x, const float* __restrict__ w,
                          const float* __restrict__ b, float* __restrict__ out)
{
    int row = blockIdx.x;
    int t   = threadIdx.x;         // 128
    const float* xr = x + row * CDIM;
    float v0 = xr[t], v1 = xr[t + 128], v2 = xr[t + 256];
    float s  = v0 + v1 + v2;
    float sq = v0*v0 + v1*v1 + v2*v2;
    __shared__ float sh[8];
    #pragma unroll
    for (int o = 16; o; o >>= 1) {
        s  += __shfl_down_sync(0xffffffffu, s,  o);
        sq += __shfl_down_sync(0xffffffffu, sq, o);
    }
    if ((t & 31) == 0) { sh[t >> 5] = s; sh[4 + (t >> 5)] = sq; }
    __syncthreads();
    __shared__ float s_mu, s_rstd;
    if (t == 0) {
        float S = sh[0] + sh[1] + sh[2] + sh[3];
        float SQ = sh[4] + sh[5] + sh[6] + sh[7];
        float mu = S / CDIM;
        s_mu = mu;
        s_rstd = rsqrtf(SQ / CDIM - mu * mu + EPSLN);
    }
    __syncthreads();
    float mu = s_mu, rstd = s_rstd;
    float* orow = out + row * CDIM;
    orow[t]       = (v0 - mu) * rstd * w[t]       + b[t];
    orow[t + 128] = (v1 - mu) * rstd * w[t + 128] + b[t + 128];
    orow[t + 256] = (v2 - mu) * rstd * w[t + 256] + b[t + 256];
}

// =============================== GEMM (R1, known-good) ===============================
// C[M,N] = A[M,K] @ W[N,K]^T + bias[N]; EPI: 0=none 1=gelu 2=+res; TRANSOUT -> (B,C,ns)
template<int EPI, bool TRANSOUT>
__global__ void gemm_kernel(const float* __restrict__ A, const float* __restrict__ W,
                            const float* __restrict__ bias, const float* __restrict__ res,
                            float* __restrict__ out, int M, int N, int K)
{
    __shared__ float As[16][64];
    __shared__ float Bs[16][64];
    int tid = threadIdx.x;               // 256
    int m0 = blockIdx.y * 64, n0 = blockIdx.x * 64;
    int lr = tid >> 2;
    int lc = (tid & 3) * 4;
    const float* Ab = A + (size_t)(m0 + lr) * K + lc;
    const float* Wb = W + (size_t)(n0 + lr) * K + lc;
    int tx = tid & 15, ty = tid >> 4;
    float acc[4][4] = {};

    for (int k0 = 0; k0 < K; k0 += 16) {
        float4 av = *(const float4*)(Ab + k0);
        float4 wv = *(const float4*)(Wb + k0);
        As[lc + 0][lr] = av.x; As[lc + 1][lr] = av.y;
        As[lc + 2][lr] = av.z; As[lc + 3][lr] = av.w;
        Bs[lc + 0][lr] = wv.x; Bs[lc + 1][lr] = wv.y;
        Bs[lc + 2][lr] = wv.z; Bs[lc + 3][lr] = wv.w;
        __syncthreads();
        #pragma unroll
        for (int kk = 0; kk < 16; kk++) {
            float4 a = *(const float4*)&As[kk][ty * 4];
            float4 bv = *(const float4*)&Bs[kk][tx * 4];
            float ar[4] = {a.x, a.y, a.z, a.w};
            float br[4] = {bv.x, bv.y, bv.z, bv.w};
            #pragma unroll
            for (int i = 0; i < 4; i++)
                #pragma unroll
                for (int j = 0; j < 4; j++)
                    acc[i][j] += ar[i] * br[j];
        }
        __syncthreads();
    }

    #pragma unroll
    for (int j = 0; j < 4; j++) {
        int n = n0 + tx * 4 + j;
        float bj = bias[n];
        #pragma unroll
        for (int i = 0; i < 4; i++) {
            int m = m0 + ty * 4 + i;
            float c = acc[i][j] + bj;
            if (EPI == 1) c = 0.5f * c * (1.0f + erff(c * 0.70710678118654752f));
            if (EPI == 2) c += res[(size_t)m * N + n];
            if (TRANSOUT) out[(size_t)(m >> 10) * N * 1024 + (size_t)n * 1024 + (m & 1023)] = c;
            else          out[(size_t)m * N + n] = c;
        }
    }
}

// ========================= Offset network (fused) =========================
__global__ void offset_kernel(const float* __restrict__ q, const float* __restrict__ dww,
                              const float* __restrict__ dwb, const float* __restrict__ lnw,
                              const float* __restrict__ lnb, const float* __restrict__ pww,
                              float* __restrict__ pos)
{
    int pix = blockIdx.x;
    int c = threadIdx.x;               // 64
    int bg = pix >> 10;
    int l  = pix & 1023;
    int y = l >> 5, x = l & 31;
    int b = bg / NGRP, g = bg % NGRP;
    int ch = g * CGRP + c;
    const float* w = dww + c * 49;
    float acc = dwb[c];
    #pragma unroll
    for (int dy = -3; dy <= 3; ++dy) {
        int yy = y + dy;
        if ((unsigned)yy >= 32u) continue;
        #pragma unroll
        for (int dx = -3; dx <= 3; ++dx) {
            int xx = x + dx;
            if ((unsigned)xx >= 32u) continue;
            acc += q[(size_t)(b * LDIM + yy * 32 + xx) * CDIM + ch] * w[(dy + 3) * 7 + (dx + 3)];
        }
    }
    float s = acc, sq = acc * acc;
    #pragma unroll
    for (int o = 16; o; o >>= 1) {
        s  += __shfl_down_sync(0xffffffffu, s,  o);
        sq += __shfl_down_sync(0xffffffffu, sq, o);
    }
    __shared__ float sh[4];
    if ((c & 31) == 0) { sh[c >> 5] = s; sh[2 + (c >> 5)] = sq; }
    __syncthreads();
    float mu  = (sh[0] + sh[1]) * (1.0f / 64.0f);
    float var = (sh[2] + sh[3]) * (1.0f / 64.0f) - mu * mu;
    float r = rsqrtf(var + EPSLN);
    float o_ = (acc - mu) * r * lnw[c] + lnb[c];
    o_ = 0.5f * o_ * (1.0f + erff(o_ * 0.70710678118654752f));
    float p0 = o_ * pww[c];
    float p1 = o_ * pww[64 + c];
    #pragma unroll
    for (int o = 16; o; o >>= 1) {
        p0 += __shfl_down_sync(0xffffffffu, p0, o);
        p1 += __shfl_down_sync(0xffffffffu, p1, o);
    }
    __shared__ float ph[4];
    if ((c & 31) == 0) { ph[c >> 5] = p0; ph[2 + (c >> 5)] = p1; }
    __syncthreads();
    if (c == 0) {
        float P0 = ph[0] + ph[1];
        float P1 = ph[2] + ph[3];
        float oy = tanhf(P0) * (2.0f / 32.0f);
        float ox = tanhf(P1) * (2.0f / 32.0f);
        float py = oy + ((y + 0.5f) / 32.0f) * 2.0f - 1.0f;
        float px = ox + ((x + 0.5f) / 32.0f) * 2.0f - 1.0f;
        pos[(size_t)bg * 2048 + l * 2 + 0] = py;
        pos[(size_t)bg * 2048 + l * 2 + 1] = px;
    }
}

// ===================== Deformable bilinear sampling =====================
__global__ void sample_kernel(const float* __restrict__ xn, const float* __restrict__ pos,
                              float* __restrict__ xs)
{
    int bn = blockIdx.x;
    int c = threadIdx.x;               // 384
    int b = bn >> 10;
    int n = bn & 1023;
    int g = c >> 6;
    float py = pos[(size_t)(b * NGRP + g) * 2048 + n * 2 + 0];
    float px = pos[(size_t)(b * NGRP + g) * 2048 + n * 2 + 1];
    float fx = (px + 1.0f) * 0.5f * 31.0f;
    float fy = (py + 1.0f) * 0.5f * 31.0f;
    float x0f = floorf(fx), y0f = floorf(fy);
    int x0 = (int)x0f, y0 = (int)y0f;
    float wx = fx - x0f, wy = fy - y0f;
    const float* base = xn + (size_t)b * LDIM * CDIM + c;
    float v = 0.0f;
    if ((unsigned)x0 < 32u && (unsigned)y0 < 32u)
        v += (1 - wx) * (1 - wy) * base[(size_t)(y0 * 32 + x0) * CDIM];
    if ((unsigned)(x0 + 1) < 32u && (unsigned)y0 < 32u)
        v += wx * (1 - wy) * base[(size_t)(y0 * 32 + x0 + 1) * CDIM];
    if ((unsigned)x0 < 32u && (unsigned)(y0 + 1) < 32u)
        v += (1 - wx) * wy * base[(size_t)((y0 + 1) * 32 + x0) * CDIM];
    if ((unsigned)(x0 + 1) < 32u && (unsigned)(y0 + 1) < 32u)
        v += wx * wy * base[(size_t)((y0 + 1) * 32 + x0 + 1) * CDIM];
    xs[(size_t)bn * CDIM + c] = v;
}

// ========== Tiled attention v3: 32 q/block, 512 threads, warp-owns-2-rows ==========
#define ATH 512
#define VPAD 34
#define ATTN_SMEM_FLOATS (32768 + 2048 + 1024 + 128*VPAD + 3972)
__device__ __forceinline__ float rpe_bilin(const float* __restrict__ s_rpe,
                                           float qgy, float qgx, float py, float px)
{
    float fy = ((qgy - py) * 0.5f + 1.0f) * 31.0f;
    float fx = ((qgx - px) * 0.5f + 1.0f) * 31.0f;
    float x0f = floorf(fx), y0f = floorf(fy);
    int xi = (int)x0f, yi = (int)y0f;
    float wx = fx - x0f, wy = fy - y0f;
    float bias = 0.0f;
    if ((unsigned)xi < 63u && (unsigned)yi < 63u)             bias += (1 - wx) * (1 - wy) * s_rpe[yi * 63 + xi];
    if ((unsigned)(xi + 1) < 63u && (unsigned)yi < 63u)       bias += wx * (1 - wy) * s_rpe[yi * 63 + xi + 1];
    if ((unsigned)xi < 63u && (unsigned)(yi + 1) < 63u)       bias += (1 - wx) * wy * s_rpe[(yi + 1) * 63 + xi];
    if ((unsigned)(xi + 1) < 63u && (unsigned)(yi + 1) < 63u) bias += wx * wy * s_rpe[(yi + 1) * 63 + xi + 1];
    return bias;
}

__global__ void attn3_kernel(const float* __restrict__ q, const float* __restrict__ kt,
                             const float* __restrict__ vt, const float* __restrict__ pos,
                             const float* __restrict__ rpe, float* __restrict__ ao)
{
    extern __shared__ float sm[];
    float* s_logit = sm;                       // 32 x 1024
    float* s_pos   = sm + 32768;               // 2048
    float* s_q     = s_pos + 2048;             // [d][32q]
    float* s_kv    = s_q + 1024;               // K: [d][64n] (2048) / V: [n][VPAD] (4352)
    float* s_rpe   = s_kv + 128 * VPAD;        // 3969 (+pad)

    int m0 = blockIdx.x * 32;
    int hh = blockIdx.y;
    int b  = blockIdx.z;
    int g  = hh >> 1;
    int t  = threadIdx.x;
    int warp = t >> 5, lane = t & 31;

    const float* posb = pos + (size_t)(b * NGRP + g) * 2048;
    for (int i = t; i < 3969; i += ATH) s_rpe[i] = rpe[hh * 3969 + i];
    for (int i = t; i < 2048; i += ATH) s_pos[i] = posb[i];
    for (int i = t; i < 1024; i += ATH) {
        int qq = i >> 5, d = i & 31;
        s_q[d * 32 + qq] = q[(size_t)(b * LDIM + m0 + qq) * CDIM + hh * HCH + d];
    }

    int q0 = 2 * warp, q1 = q0 + 1;
    int mg0 = m0 + q0, mg1 = m0 + q1;
    float qgy0 = ((float)(mg0 >> 5) + 0.5f) * (1.0f / 16.0f) - 1.0f;
    float qgx0 = ((float)(mg0 & 31) + 0.5f) * (1.0f / 16.0f) - 1.0f;
    float qgy1 = ((float)(mg1 >> 5) + 0.5f) * (1.0f / 16.0f) - 1.0f;
    float qgx1 = ((float)(mg1 & 31) + 0.5f) * (1.0f / 16.0f) - 1.0f;

    const float* ktb = kt + ((size_t)b * CDIM + hh * HCH) * (size_t)NSD;
    const float scale = 0.17677669529663687f;
    float mrun0 = -1e30f, mrun1 = -1e30f;

    for (int nc = 0; nc < 1024; nc += 64) {
        __syncthreads();
        #pragma unroll
        for (int i = t; i < 2048; i += ATH)
            s_kv[i] = ktb[(size_t)(i >> 6) * NSD + nc + (i & 63)];
        __syncthreads();

        float a00 = 0.f, a01 = 0.f, a10 = 0.f, a11 = 0.f;
        #pragma unroll
        for (int d = 0; d < 32; d++) {
            float2 k2 = *(const float2*)&s_kv[d * 64 + 2 * lane];
            float qa = s_q[d * 32 + q0];
            float qb = s_q[d * 32 + q1];
            a00 += qa * k2.x; a01 += qa * k2.y;
            a10 += qb * k2.x; a11 += qb * k2.y;
        }
        int n0 = nc + 2 * lane;
        float py0 = s_pos[2 * n0],     px0 = s_pos[2 * n0 + 1];
        float py1 = s_pos[2 * n0 + 2], px1 = s_pos[2 * n0 + 3];
        float v00 = a00 * scale + rpe_bilin(s_rpe, qgy0, qgx0, py0, px0);
        float v01 = a01 * scale + rpe_bilin(s_rpe, qgy0, qgx0, py1, px1);
        float v10 = a10 * scale + rpe_bilin(s_rpe, qgy1, qgx1, py0, px0);
        float v11 = a11 * scale + rpe_bilin(s_rpe, qgy1, qgx1, py1, px1);
        *(float2*)&s_logit[q0 * 1024 + n0] = make_float2(v00, v01);
        *(float2*)&s_logit[q1 * 1024 + n0] = make_float2(v10, v11);
        mrun0 = fmaxf(mrun0, fmaxf(v00, v01));
        mrun1 = fmaxf(mrun1, fmaxf(v10, v11));
    }
    #pragma unroll
    for (int o = 16; o; o >>= 1) {
        mrun0 = fmaxf(mrun0, __shfl_xor_sync(0xffffffffu, mrun0, o));
        mrun1 = fmaxf(mrun1, __shfl_xor_sync(0xffffffffu, mrun1, o));
    }
    __syncwarp();

    // exp + sum (warp-local: this warp wrote these rows)
    float* L0 = s_logit + q0 * 1024;
    float* L1 = s_logit + q1 * 1024;
    float sum0 = 0.f, sum1 = 0.f;
    #pragma unroll
    for (int k = 0; k < 8; k++) {
        float4 p = *(float4*)&L0[lane * 4 + k * 128];
        p.x = __expf(p.x - mrun0); p.y = __expf(p.y - mrun0);
        p.z = __expf(p.z - mrun0); p.w = __expf(p.w - mrun0);
        sum0 += p.x + p.y + p.z + p.w;
        *(float4*)&L0[lane * 4 + k * 128] = p;
        float4 r = *(float4*)&L1[lane * 4 + k * 128];
        r.x = __expf(r.x - mrun1); r.y = __expf(r.y - mrun1);
        r.z = __expf(r.z - mrun1); r.w = __expf(r.w - mrun1);
        sum1 += r.x + r.y + r.z + r.w;
        *(float4*)&L1[lane * 4 + k * 128] = r;
    }
    #pragma unroll
    for (int o = 16; o; o >>= 1) {
        sum0 += __shfl_xor_sync(0xffffffffu, sum0, o);
        sum1 += __shfl_xor_sync(0xffffffffu, sum1, o);
    }
    float rinv0 = 1.0f / sum0;
    float rinv1 = 1.0f / sum1;
    __syncwarp();

    // AV: lane<16 -> row q0, lane>=16 -> row q1; each lane owns 2 channels
    const float* vtb = vt + ((size_t)b * CDIM + hh * HCH) * (size_t)NSD;
    int qq = (lane < 16) ? q0 : q1;
    int d0 = 2 * (lane & 15);
    float accA = 0.f, accB = 0.f;

    for (int nc = 0; nc < 1024; nc += 128) {
        __syncthreads();
        #pragma unroll
        for (int i = t; i < 4096; i += ATH) {
            int d = i >> 7, n = i & 127;
            s_kv[n * VPAD + d] = vtb[(size_t)d * NSD + nc + n];
        }
        __syncthreads();
        const float* Lr = s_logit + qq * 1024 + nc;
        #pragma unroll 8
        for (int n = 0; n < 128; n += 4) {
            float4 p4 = *(const float4*)&Lr[n];
            float2 va = *(const float2*)&s_kv[(n + 0) * VPAD + d0];
            float2 vb = *(const float2*)&s_kv[(n + 1) * VPAD + d0];
            float2 vc = *(const float2*)&s_kv[(n + 2) * VPAD + d0];
            float2 vd = *(const float2*)&s_kv[(n + 3) * VPAD + d0];
            accA += p4.x * va.x + p4.y * vb.x + p4.z * vc.x + p4.w * vd.x;
            accB += p4.x * va.y + p4.y * vb.y + p4.z * vc.y + p4.w * vd.y;
        }
    }
    float rinv = (lane < 16) ? rinv0 : rinv1;
    float2 o2 = make_float2(accA * rinv, accB * rinv);
    *(float2*)&ao[(size_t)(b * LDIM + m0 + qq) * CDIM + hh * HCH + d0] = o2;
}

// =============================== host ===============================
extern "C" void kernel_launch(void* const* d_in, const int* in_sizes, int n_in,
                              void* d_out, int out_size)
{
    const float* x     = (const float*)d_in[0];
    const float* n1w   = (const float*)d_in[1];
    const float* n1b   = (const float*)d_in[2];
    const float* wq    = (const float*)d_in[3];
    const float* bq    = (const float*)d_in[4];
    const float* wk    = (const float*)d_in[5];
    const float* bk    = (const float*)d_in[6];
    const float* wv    = (const float*)d_in[7];
    const float* bv    = (const float*)d_in[8];
    const float* wo    = (const float*)d_in[9];
    const float* bo    = (const float*)d_in[10];
    const float* dww   = (const float*)d_in[11];
    const float* dwb   = (const float*)d_in[12];
    const float* lnw   = (const float*)d_in[13];
    const float* lnb   = (const float*)d_in[14];
    const float* pww   = (const float*)d_in[15];
    const float* rpe   = (const float*)d_in[16];
    const float* n2w   = (const float*)d_in[17];
    const float* n2b   = (const float*)d_in[18];
    const float* fc1w  = (const float*)d_in[19];
    const float* fc1b  = (const float*)d_in[20];
    const float* fc2w  = (const float*)d_in[21];
    const float* fc2b  = (const float*)d_in[22];
    float* out = (float*)d_out;

    float *p_xn, *p_q, *p_pos, *p_xs, *p_kt, *p_vt, *p_ao, *p_x2, *p_ln2, *p_h1;
    cudaGetSymbolAddress((void**)&p_xn,  g_xn);
    cudaGetSymbolAddress((void**)&p_q,   g_q);
    cudaGetSymbolAddress((void**)&p_pos, g_pos);
    cudaGetSymbolAddress((void**)&p_xs,  g_xs);
    cudaGetSymbolAddress((void**)&p_kt,  g_kt);
    cudaGetSymbolAddress((void**)&p_vt,  g_vt);
    cudaGetSymbolAddress((void**)&p_ao,  g_ao);
    cudaGetSymbolAddress((void**)&p_x2,  g_x2);
    cudaGetSymbolAddress((void**)&p_ln2, g_ln2);
    cudaGetSymbolAddress((void**)&p_h1,  g_h1);

    const int M = BX * LDIM;   // 2048
    const int attn_smem = ATTN_SMEM_FLOATS * (int)sizeof(float);
    cudaFuncSetAttribute(attn3_kernel, cudaFuncAttributeMaxDynamicSharedMemorySize, attn_smem);

    ln_kernel<<<M, 128>>>(x, n1w, n1b, p_xn);
    gemm_kernel<0, false><<<dim3(CDIM / 64, M / 64), 256>>>(p_xn, wq, bq, nullptr, p_q, M, CDIM, CDIM);
    offset_kernel<<<BX * NGRP * 1024, 64>>>(p_q, dww, dwb, lnw, lnb, pww, p_pos);
    sample_kernel<<<BX * NSD, CDIM>>>(p_xn, p_pos, p_xs);
    gemm_kernel<0, true><<<dim3(CDIM / 64, M / 64), 256>>>(p_xs, wk, bk, nullptr, p_kt, M, CDIM, CDIM);
    gemm_kernel<0, true><<<dim3(CDIM / 64, M / 64), 256>>>(p_xs, wv, bv, nullptr, p_vt, M, CDIM, CDIM);
    attn3_kernel<<<dim3(32, NHD, BX), ATH, attn_smem>>>(p_q, p_kt, p_vt, p_pos, rpe, p_ao);
    gemm_kernel<2, false><<<dim3(CDIM / 64, M / 64), 256>>>(p_ao, wo, bo, x, p_x2, M, CDIM, CDIM);
    ln_kernel<<<M, 128>>>(p_x2, n2w, n2b, p_ln2);
    gemm_kernel<1, false><<<dim3(HIDD / 64, M / 64), 256>>>(p_ln2, fc1w, fc1b, nullptr, p_h1, M, HIDD, CDIM);
    gemm_kernel<2, false><<<dim3(CDIM / 64, M / 64), 256>>>(p_h1, fc2w, fc2b, p_x2, out, M, CDIM, HIDD);
}

// round 4
// speedup vs baseline: 1.8288x; 1.5296x over previous
#include <cuda_runtime.h>
#include <cuda_fp16.h>
#include <mma.h>
#include <math.h>
using namespace nvcuda;

// ---- problem constants ----
#define BX   2
#define CDIM 384
#define NHD  12
#define NGRP 6
#define CGRP 64
#define HCH  32
#define LDIM 1024
#define NSD  1024
#define HIDD 1536
#define EPSLN 1e-5f

// ---- scratch ----
__device__ float  g_xn [BX*LDIM*CDIM];
__device__ __half g_xnh[BX*LDIM*CDIM];
__device__ float  g_q  [BX*LDIM*CDIM];
__device__ float  g_pos[BX*NGRP*NSD*2];
__device__ __half g_xsh[BX*NSD*CDIM];
__device__ float  g_kt [BX*CDIM*NSD];
__device__ float  g_vt [BX*CDIM*NSD];
__device__ __half g_aoh[BX*LDIM*CDIM];
__device__ float  g_x2 [BX*LDIM*CDIM];
__device__ __half g_ln2h[BX*LDIM*CDIM];
__device__ __half g_h1h[BX*LDIM*HIDD];
// half weights
__device__ __half g_wqh[CDIM*CDIM];
__device__ __half g_wkh[CDIM*CDIM];
__device__ __half g_wvh[CDIM*CDIM];
__device__ __half g_woh[CDIM*CDIM];
__device__ __half g_f1h[HIDD*CDIM];
__device__ __half g_f2h[CDIM*HIDD];

// =============================== convert f32 -> f16 ===============================
__global__ void f2h_kernel(const float* __restrict__ src, __half* __restrict__ dst)
{
    int i = blockIdx.x * 256 + threadIdx.x;
    float4 v = ((const float4*)src)[i];
    ((__half2*)dst)[2*i]   = __floats2half2_rn(v.x, v.y);
    ((__half2*)dst)[2*i+1] = __floats2half2_rn(v.z, v.w);
}

// =============================== LayerNorm ===============================
// WRITE_F32 / WRITE_H16 control outputs
template<bool WF, bool WH>
__global__ void ln_kernel(const float* __restrict__ x, const float* __restrict__ w,
                          const float* __restrict__ b, float* __restrict__ out,
                          __half* __restrict__ outh)
{
    int row = blockIdx.x;
    int t   = threadIdx.x;         // 128
    const float* xr = x + row * CDIM;
    float v0 = xr[t], v1 = xr[t + 128], v2 = xr[t + 256];
    float s  = v0 + v1 + v2;
    float sq = v0*v0 + v1*v1 + v2*v2;
    __shared__ float sh[8];
    #pragma unroll
    for (int o = 16; o; o >>= 1) {
        s  += __shfl_down_sync(0xffffffffu, s,  o);
        sq += __shfl_down_sync(0xffffffffu, sq, o);
    }
    if ((t & 31) == 0) { sh[t >> 5] = s; sh[4 + (t >> 5)] = sq; }
    __syncthreads();
    __shared__ float s_mu, s_rstd;
    if (t == 0) {
        float S = sh[0] + sh[1] + sh[2] + sh[3];
        float SQ = sh[4] + sh[5] + sh[6] + sh[7];
        float mu = S / CDIM;
        s_mu = mu;
        s_rstd = rsqrtf(SQ / CDIM - mu * mu + EPSLN);
    }
    __syncthreads();
    float mu = s_mu, rstd = s_rstd;
    float r0 = (v0 - mu) * rstd * w[t]       + b[t];
    float r1 = (v1 - mu) * rstd * w[t + 128] + b[t + 128];
    float r2 = (v2 - mu) * rstd * w[t + 256] + b[t + 256];
    if (WF) {
        float* orow = out + row * CDIM;
        orow[t] = r0; orow[t + 128] = r1; orow[t + 256] = r2;
    }
    if (WH) {
        __half* hrow = outh + row * CDIM;
        hrow[t] = __float2half(r0); hrow[t + 128] = __float2half(r1); hrow[t + 256] = __float2half(r2);
    }
}

// =============================== WMMA GEMM ===============================
// C[M,N] = A[M,K](half) @ W[N,K](half)^T + bias; fp32 accum.
// EPI: 0=none 1=gelu 2=+res; TRANSOUT -> (B,C,ns) f32; OUTH -> half output
template<int EPI, bool TRANSOUT, bool OUTH>
__global__ void hgemm_kernel(const __half* __restrict__ A, const __half* __restrict__ W,
                             const float* __restrict__ bias, const float* __restrict__ res,
                             void* __restrict__ outv, int M, int N, int K)
{
    __shared__ __half As[64][40];
    __shared__ __half Bs[64][40];
    __shared__ float  Cs[64][64];
    int tid = threadIdx.x;               // 128
    int m0 = blockIdx.y * 64, n0 = blockIdx.x * 64;
    int warp = tid >> 5;
    int wy = warp >> 1, wx = warp & 1;   // 2x2 warps, each 32x32

    wmma::fragment<wmma::accumulator, 16,16,16, float> acc[2][2];
    #pragma unroll
    for (int i = 0; i < 2; i++)
        #pragma unroll
        for (int j = 0; j < 2; j++)
            wmma::fill_fragment(acc[i][j], 0.0f);

    for (int k0 = 0; k0 < K; k0 += 32) {
        #pragma unroll
        for (int j = 0; j < 2; j++) {
            int idx = tid + j * 128;
            int r = idx >> 2, c = (idx & 3) * 8;
            *(uint4*)&As[r][c] = *(const uint4*)&A[(size_t)(m0 + r) * K + k0 + c];
            *(uint4*)&Bs[r][c] = *(const uint4*)&W[(size_t)(n0 + r) * K + k0 + c];
        }
        __syncthreads();
        #pragma unroll
        for (int kk = 0; kk < 32; kk += 16) {
            wmma::fragment<wmma::matrix_a, 16,16,16, __half, wmma::row_major> a0, a1;
            wmma::fragment<wmma::matrix_b, 16,16,16, __half, wmma::col_major> b0, b1;
            wmma::load_matrix_sync(a0, &As[wy * 32][kk], 40);
            wmma::load_matrix_sync(a1, &As[wy * 32 + 16][kk], 40);
            wmma::load_matrix_sync(b0, &Bs[wx * 32][kk], 40);
            wmma::load_matrix_sync(b1, &Bs[wx * 32 + 16][kk], 40);
            wmma::mma_sync(acc[0][0], a0, b0, acc[0][0]);
            wmma::mma_sync(acc[0][1], a0, b1, acc[0][1]);
            wmma::mma_sync(acc[1][0], a1, b0, acc[1][0]);
            wmma::mma_sync(acc[1][1], a1, b1, acc[1][1]);
        }
        __syncthreads();
    }
    #pragma unroll
    for (int i = 0; i < 2; i++)
        #pragma unroll
        for (int j = 0; j < 2; j++)
            wmma::store_matrix_sync(&Cs[wy * 32 + i * 16][wx * 32 + j * 16], acc[i][j], 64, wmma::mem_row_major);
    __syncthreads();

    for (int idx = tid; idx < 4096; idx += 128) {
        int mi = idx >> 6, ni = idx & 63;
        int m = m0 + mi, n = n0 + ni;
        float c = Cs[mi][ni] + bias[n];
        if (EPI == 1) c = 0.5f * c * (1.0f + erff(c * 0.70710678118654752f));
        if (EPI == 2) c += res[(size_t)m * N + n];
        if (OUTH) {
            ((__half*)outv)[(size_t)m * N + n] = __float2half(c);
        } else if (TRANSOUT) {
            ((float*)outv)[(size_t)(m >> 10) * N * 1024 + (size_t)n * 1024 + (m & 1023)] = c;
        } else {
            ((float*)outv)[(size_t)m * N + n] = c;
        }
    }
}

// ========================= Offset network (fused) =========================
__global__ void offset_kernel(const float* __restrict__ q, const float* __restrict__ dww,
                              const float* __restrict__ dwb, const float* __restrict__ lnw,
                              const float* __restrict__ lnb, const float* __restrict__ pww,
                              float* __restrict__ pos)
{
    int pix = blockIdx.x;
    int c = threadIdx.x;               // 64
    int bg = pix >> 10;
    int l  = pix & 1023;
    int y = l >> 5, x = l & 31;
    int b = bg / NGRP, g = bg % NGRP;
    int ch = g * CGRP + c;
    const float* w = dww + c * 49;
    float acc = dwb[c];
    #pragma unroll
    for (int dy = -3; dy <= 3; ++dy) {
        int yy = y + dy;
        if ((unsigned)yy >= 32u) continue;
        #pragma unroll
        for (int dx = -3; dx <= 3; ++dx) {
            int xx = x + dx;
            if ((unsigned)xx >= 32u) continue;
            acc += q[(size_t)(b * LDIM + yy * 32 + xx) * CDIM + ch] * w[(dy + 3) * 7 + (dx + 3)];
        }
    }
    float s = acc, sq = acc * acc;
    #pragma unroll
    for (int o = 16; o; o >>= 1) {
        s  += __shfl_down_sync(0xffffffffu, s,  o);
        sq += __shfl_down_sync(0xffffffffu, sq, o);
    }
    __shared__ float sh[4];
    if ((c & 31) == 0) { sh[c >> 5] = s; sh[2 + (c >> 5)] = sq; }
    __syncthreads();
    float mu  = (sh[0] + sh[1]) * (1.0f / 64.0f);
    float var = (sh[2] + sh[3]) * (1.0f / 64.0f) - mu * mu;
    float r = rsqrtf(var + EPSLN);
    float o_ = (acc - mu) * r * lnw[c] + lnb[c];
    o_ = 0.5f * o_ * (1.0f + erff(o_ * 0.70710678118654752f));
    float p0 = o_ * pww[c];
    float p1 = o_ * pww[64 + c];
    #pragma unroll
    for (int o = 16; o; o >>= 1) {
        p0 += __shfl_down_sync(0xffffffffu, p0, o);
        p1 += __shfl_down_sync(0xffffffffu, p1, o);
    }
    __shared__ float ph[4];
    if ((c & 31) == 0) { ph[c >> 5] = p0; ph[2 + (c >> 5)] = p1; }
    __syncthreads();
    if (c == 0) {
        float P0 = ph[0] + ph[1];
        float P1 = ph[2] + ph[3];
        float oy = tanhf(P0) * (2.0f / 32.0f);
        float ox = tanhf(P1) * (2.0f / 32.0f);
        float py = oy + ((y + 0.5f) / 32.0f) * 2.0f - 1.0f;
        float px = ox + ((x + 0.5f) / 32.0f) * 2.0f - 1.0f;
        pos[(size_t)bg * 2048 + l * 2 + 0] = py;
        pos[(size_t)bg * 2048 + l * 2 + 1] = px;
    }
}

// ===================== Deformable bilinear sampling (half out) =====================
__global__ void sample_kernel(const float* __restrict__ xn, const float* __restrict__ pos,
                              __half* __restrict__ xs)
{
    int bn = blockIdx.x;
    int c = threadIdx.x;               // 384
    int b = bn >> 10;
    int n = bn & 1023;
    int g = c >> 6;
    float py = pos[(size_t)(b * NGRP + g) * 2048 + n * 2 + 0];
    float px = pos[(size_t)(b * NGRP + g) * 2048 + n * 2 + 1];
    float fx = (px + 1.0f) * 0.5f * 31.0f;
    float fy = (py + 1.0f) * 0.5f * 31.0f;
    float x0f = floorf(fx), y0f = floorf(fy);
    int x0 = (int)x0f, y0 = (int)y0f;
    float wx = fx - x0f, wy = fy - y0f;
    const float* base = xn + (size_t)b * LDIM * CDIM + c;
    float v = 0.0f;
    if ((unsigned)x0 < 32u && (unsigned)y0 < 32u)
        v += (1 - wx) * (1 - wy) * base[(size_t)(y0 * 32 + x0) * CDIM];
    if ((unsigned)(x0 + 1) < 32u && (unsigned)y0 < 32u)
        v += wx * (1 - wy) * base[(size_t)(y0 * 32 + x0 + 1) * CDIM];
    if ((unsigned)x0 < 32u && (unsigned)(y0 + 1) < 32u)
        v += (1 - wx) * wy * base[(size_t)((y0 + 1) * 32 + x0) * CDIM];
    if ((unsigned)(x0 + 1) < 32u && (unsigned)(y0 + 1) < 32u)
        v += wx * wy * base[(size_t)((y0 + 1) * 32 + x0 + 1) * CDIM];
    xs[(size_t)bn * CDIM + c] = __float2half(v);
}

// ========== Tiled attention v3 (half ao out) ==========
#define ATH 512
#define VPAD 34
#define ATTN_SMEM_FLOATS (32768 + 2048 + 1024 + 128*VPAD + 3972)
__device__ __forceinline__ float rpe_bilin(const float* __restrict__ s_rpe,
                                           float qgy, float qgx, float py, float px)
{
    float fy = ((qgy - py) * 0.5f + 1.0f) * 31.0f;
    float fx = ((qgx - px) * 0.5f + 1.0f) * 31.0f;
    float x0f = floorf(fx), y0f = floorf(fy);
    int xi = (int)x0f, yi = (int)y0f;
    float wx = fx - x0f, wy = fy - y0f;
    float bias = 0.0f;
    if ((unsigned)xi < 63u && (unsigned)yi < 63u)             bias += (1 - wx) * (1 - wy) * s_rpe[yi * 63 + xi];
    if ((unsigned)(xi + 1) < 63u && (unsigned)yi < 63u)       bias += wx * (1 - wy) * s_rpe[yi * 63 + xi + 1];
    if ((unsigned)xi < 63u && (unsigned)(yi + 1) < 63u)       bias += (1 - wx) * wy * s_rpe[(yi + 1) * 63 + xi];
    if ((unsigned)(xi + 1) < 63u && (unsigned)(yi + 1) < 63u) bias += wx * wy * s_rpe[(yi + 1) * 63 + xi + 1];
    return bias;
}

__global__ void attn3_kernel(const float* __restrict__ q, const float* __restrict__ kt,
                             const float* __restrict__ vt, const float* __restrict__ pos,
                             const float* __restrict__ rpe, __half* __restrict__ ao)
{
    extern __shared__ float sm[];
    float* s_logit = sm;                       // 32 x 1024
    float* s_pos   = sm + 32768;               // 2048
    float* s_q     = s_pos + 2048;             // [d][32q]
    float* s_kv    = s_q + 1024;               // K: [d][64n] / V: [n][VPAD]
    float* s_rpe   = s_kv + 128 * VPAD;        // 3969 (+pad)

    int m0 = blockIdx.x * 32;
    int hh = blockIdx.y;
    int b  = blockIdx.z;
    int g  = hh >> 1;
    int t  = threadIdx.x;
    int warp = t >> 5, lane = t & 31;

    const float* posb = pos + (size_t)(b * NGRP + g) * 2048;
    for (int i = t; i < 3969; i += ATH) s_rpe[i] = rpe[hh * 3969 + i];
    for (int i = t; i < 2048; i += ATH) s_pos[i] = posb[i];
    for (int i = t; i < 1024; i += ATH) {
        int qq = i >> 5, d = i & 31;
        s_q[d * 32 + qq] = q[(size_t)(b * LDIM + m0 + qq) * CDIM + hh * HCH + d];
    }

    int q0 = 2 * warp, q1 = q0 + 1;
    int mg0 = m0 + q0, mg1 = m0 + q1;
    float qgy0 = ((float)(mg0 >> 5) + 0.5f) * (1.0f / 16.0f) - 1.0f;
    float qgx0 = ((float)(mg0 & 31) + 0.5f) * (1.0f / 16.0f) - 1.0f;
    float qgy1 = ((float)(mg1 >> 5) + 0.5f) * (1.0f / 16.0f) - 1.0f;
    float qgx1 = ((float)(mg1 & 31) + 0.5f) * (1.0f / 16.0f) - 1.0f;

    const float* ktb = kt + ((size_t)b * CDIM + hh * HCH) * (size_t)NSD;
    const float scale = 0.17677669529663687f;
    float mrun0 = -1e30f, mrun1 = -1e30f;

    for (int nc = 0; nc < 1024; nc += 64) {
        __syncthreads();
        #pragma unroll
        for (int i = t; i < 2048; i += ATH)
            s_kv[i] = ktb[(size_t)(i >> 6) * NSD + nc + (i & 63)];
        __syncthreads();

        float a00 = 0.f, a01 = 0.f, a10 = 0.f, a11 = 0.f;
        #pragma unroll
        for (int d = 0; d < 32; d++) {
            float2 k2 = *(const float2*)&s_kv[d * 64 + 2 * lane];
            float qa = s_q[d * 32 + q0];
            float qb = s_q[d * 32 + q1];
            a00 += qa * k2.x; a01 += qa * k2.y;
            a10 += qb * k2.x; a11 += qb * k2.y;
        }
        int n0 = nc + 2 * lane;
        float py0 = s_pos[2 * n0],     px0 = s_pos[2 * n0 + 1];
        float py1 = s_pos[2 * n0 + 2], px1 = s_pos[2 * n0 + 3];
        float v00 = a00 * scale + rpe_bilin(s_rpe, qgy0, qgx0, py0, px0);
        float v01 = a01 * scale + rpe_bilin(s_rpe, qgy0, qgx0, py1, px1);
        float v10 = a10 * scale + rpe_bilin(s_rpe, qgy1, qgx1, py0, px0);
        float v11 = a11 * scale + rpe_bilin(s_rpe, qgy1, qgx1, py1, px1);
        *(float2*)&s_logit[q0 * 1024 + n0] = make_float2(v00, v01);
        *(float2*)&s_logit[q1 * 1024 + n0] = make_float2(v10, v11);
        mrun0 = fmaxf(mrun0, fmaxf(v00, v01));
        mrun1 = fmaxf(mrun1, fmaxf(v10, v11));
    }
    #pragma unroll
    for (int o = 16; o; o >>= 1) {
        mrun0 = fmaxf(mrun0, __shfl_xor_sync(0xffffffffu, mrun0, o));
        mrun1 = fmaxf(mrun1, __shfl_xor_sync(0xffffffffu, mrun1, o));
    }
    __syncwarp();

    float* L0 = s_logit + q0 * 1024;
    float* L1 = s_logit + q1 * 1024;
    float sum0 = 0.f, sum1 = 0.f;
    #pragma unroll
    for (int k = 0; k < 8; k++) {
        float4 p = *(float4*)&L0[lane * 4 + k * 128];
        p.x = __expf(p.x - mrun0); p.y = __expf(p.y - mrun0);
        p.z = __expf(p.z - mrun0); p.w = __expf(p.w - mrun0);
        sum0 += p.x + p.y + p.z + p.w;
        *(float4*)&L0[lane * 4 + k * 128] = p;
        float4 r = *(float4*)&L1[lane * 4 + k * 128];
        r.x = __expf(r.x - mrun1); r.y = __expf(r.y - mrun1);
        r.z = __expf(r.z - mrun1); r.w = __expf(r.w - mrun1);
        sum1 += r.x + r.y + r.z + r.w;
        *(float4*)&L1[lane * 4 + k * 128] = r;
    }
    #pragma unroll
    for (int o = 16; o; o >>= 1) {
        sum0 += __shfl_xor_sync(0xffffffffu, sum0, o);
        sum1 += __shfl_xor_sync(0xffffffffu, sum1, o);
    }
    float rinv0 = 1.0f / sum0;
    float rinv1 = 1.0f / sum1;
    __syncwarp();

    const float* vtb = vt + ((size_t)b * CDIM + hh * HCH) * (size_t)NSD;
    int qq = (lane < 16) ? q0 : q1;
    int d0 = 2 * (lane & 15);
    float accA = 0.f, accB = 0.f;

    for (int nc = 0; nc < 1024; nc += 128) {
        __syncthreads();
        #pragma unroll
        for (int i = t; i < 4096; i += ATH) {
            int d = i >> 7, n = i & 127;
            s_kv[n * VPAD + d] = vtb[(size_t)d * NSD + nc + n];
        }
        __syncthreads();
        const float* Lr = s_logit + qq * 1024 + nc;
        #pragma unroll 8
        for (int n = 0; n < 128; n += 4) {
            float4 p4 = *(const float4*)&Lr[n];
            float2 va = *(const float2*)&s_kv[(n + 0) * VPAD + d0];
            float2 vb = *(const float2*)&s_kv[(n + 1) * VPAD + d0];
            float2 vc = *(const float2*)&s_kv[(n + 2) * VPAD + d0];
            float2 vd = *(const float2*)&s_kv[(n + 3) * VPAD + d0];
            accA += p4.x * va.x + p4.y * vb.x + p4.z * vc.x + p4.w * vd.x;
            accB += p4.x * va.y + p4.y * vb.y + p4.z * vc.y + p4.w * vd.y;
        }
    }
    float rinv = (lane < 16) ? rinv0 : rinv1;
    __half2 o2 = __floats2half2_rn(accA * rinv, accB * rinv);
    *(__half2*)&ao[(size_t)(b * LDIM + m0 + qq) * CDIM + hh * HCH + d0] = o2;
}

// =============================== host ===============================
extern "C" void kernel_launch(void* const* d_in, const int* in_sizes, int n_in,
                              void* d_out, int out_size)
{
    const float* x     = (const float*)d_in[0];
    const float* n1w   = (const float*)d_in[1];
    const float* n1b   = (const float*)d_in[2];
    const float* wq    = (const float*)d_in[3];
    const float* bq    = (const float*)d_in[4];
    const float* wk    = (const float*)d_in[5];
    const float* bk    = (const float*)d_in[6];
    const float* wv    = (const float*)d_in[7];
    const float* bv    = (const float*)d_in[8];
    const float* wo    = (const float*)d_in[9];
    const float* bo    = (const float*)d_in[10];
    const float* dww   = (const float*)d_in[11];
    const float* dwb   = (const float*)d_in[12];
    const float* lnw   = (const float*)d_in[13];
    const float* lnb   = (const float*)d_in[14];
    const float* pww   = (const float*)d_in[15];
    const float* rpe   = (const float*)d_in[16];
    const float* n2w   = (const float*)d_in[17];
    const float* n2b   = (const float*)d_in[18];
    const float* fc1w  = (const float*)d_in[19];
    const float* fc1b  = (const float*)d_in[20];
    const float* fc2w  = (const float*)d_in[21];
    const float* fc2b  = (const float*)d_in[22];
    float* out = (float*)d_out;

    float *p_xn, *p_q, *p_pos, *p_kt, *p_vt, *p_x2;
    __half *p_xnh, *p_xsh, *p_aoh, *p_ln2h, *p_h1h;
    __half *p_wqh, *p_wkh, *p_wvh, *p_woh, *p_f1h, *p_f2h;
    cudaGetSymbolAddress((void**)&p_xn,  g_xn);
    cudaGetSymbolAddress((void**)&p_xnh, g_xnh);
    cudaGetSymbolAddress((void**)&p_q,   g_q);
    cudaGetSymbolAddress((void**)&p_pos, g_pos);
    cudaGetSymbolAddress((void**)&p_xsh, g_xsh);
    cudaGetSymbolAddress((void**)&p_kt,  g_kt);
    cudaGetSymbolAddress((void**)&p_vt,  g_vt);
    cudaGetSymbolAddress((void**)&p_aoh, g_aoh);
    cudaGetSymbolAddress((void**)&p_x2,  g_x2);
    cudaGetSymbolAddress((void**)&p_ln2h, g_ln2h);
    cudaGetSymbolAddress((void**)&p_h1h, g_h1h);
    cudaGetSymbolAddress((void**)&p_wqh, g_wqh);
    cudaGetSymbolAddress((void**)&p_wkh, g_wkh);
    cudaGetSymbolAddress((void**)&p_wvh, g_wvh);
    cudaGetSymbolAddress((void**)&p_woh, g_woh);
    cudaGetSymbolAddress((void**)&p_f1h, g_f1h);
    cudaGetSymbolAddress((void**)&p_f2h, g_f2h);

    const int M = BX * LDIM;   // 2048
    const int attn_smem = ATTN_SMEM_FLOATS * (int)sizeof(float);
    cudaFuncSetAttribute(attn3_kernel, cudaFuncAttributeMaxDynamicSharedMemorySize, attn_smem);

    // weight conversions (147456 = 144*1024 ; 589824 = 576*1024)
    f2h_kernel<<<144, 256>>>(wq, p_wqh);
    f2h_kernel<<<144, 256>>>(wk, p_wkh);
    f2h_kernel<<<144, 256>>>(wv, p_wvh);
    f2h_kernel<<<144, 256>>>(wo, p_woh);
    f2h_kernel<<<576, 256>>>(fc1w, p_f1h);
    f2h_kernel<<<576, 256>>>(fc2w, p_f2h);

    // LN1 -> xn (f32) + xn_h
    ln_kernel<true, true><<<M, 128>>>(x, n1w, n1b, p_xn, p_xnh);
    // q projection (f32 out)
    hgemm_kernel<0, false, false><<<dim3(CDIM/64, M/64), 128>>>(p_xnh, p_wqh, bq, nullptr, p_q, M, CDIM, CDIM);
    // offset network -> pos
    offset_kernel<<<BX * NGRP * 1024, 64>>>(p_q, dww, dwb, lnw, lnb, pww, p_pos);
    // deformable sampling -> xs_h
    sample_kernel<<<BX * NSD, CDIM>>>(p_xn, p_pos, p_xsh);
    // k, v projections (TRANSOUT f32)
    hgemm_kernel<0, true, false><<<dim3(CDIM/64, M/64), 128>>>(p_xsh, p_wkh, bk, nullptr, p_kt, M, CDIM, CDIM);
    hgemm_kernel<0, true, false><<<dim3(CDIM/64, M/64), 128>>>(p_xsh, p_wvh, bv, nullptr, p_vt, M, CDIM, CDIM);
    // fused attention -> ao_h
    attn3_kernel<<<dim3(32, NHD, BX), ATH, attn_smem>>>(p_q, p_kt, p_vt, p_pos, rpe, p_aoh);
    // output projection + residual -> x2 (f32)
    hgemm_kernel<2, false, false><<<dim3(CDIM/64, M/64), 128>>>(p_aoh, p_woh, bo, x, p_x2, M, CDIM, CDIM);
    // LN2 -> ln2_h
    ln_kernel<false, true><<<M, 128>>>(p_x2, n2w, n2b, nullptr, p_ln2h);
    // fc1 + gelu -> h1_h
    hgemm_kernel<1, false, true><<<dim3(HIDD/64, M/64), 128>>>(p_ln2h, p_f1h, fc1b, nullptr, p_h1h, M, HIDD, CDIM);
    // fc2 + residual -> out (f32)
    hgemm_kernel<2, false, false><<<dim3(CDIM/64, M/64), 128>>>(p_h1h, p_f2h, fc2b, p_x2, out, M, CDIM, HIDD);
}

// round 5
// speedup vs baseline: 1.8296x; 1.0005x over previous
#include <cuda_runtime.h>
#include <cuda_fp16.h>
#include <mma.h>
#include <math.h>
using namespace nvcuda;

// ---- problem constants ----
#define BX   2
#define CDIM 384
#define NHD  12
#define NGRP 6
#define CGRP 64
#define HCH  32
#define LDIM 1024
#define NSD  1024
#define HIDD 1536
#define EPSLN 1e-5f

// ---- scratch ----
__device__ float  g_xn [BX*LDIM*CDIM];
__device__ __half g_xnh[BX*LDIM*CDIM];
__device__ float  g_q  [BX*LDIM*CDIM];
__device__ float  g_pos[BX*NGRP*NSD*2];
__device__ __half g_xsh[BX*NSD*CDIM];
__device__ float  g_kt [BX*CDIM*NSD];
__device__ float  g_vt [BX*CDIM*NSD];
__device__ __half g_aoh[BX*LDIM*CDIM];
__device__ float  g_x2 [BX*LDIM*CDIM];
__device__ __half g_ln2h[BX*LDIM*CDIM];
__device__ __half g_h1h[BX*LDIM*HIDD];
// half weights
__device__ __half g_wqh[CDIM*CDIM];
__device__ __half g_wkh[CDIM*CDIM];
__device__ __half g_wvh[CDIM*CDIM];
__device__ __half g_woh[CDIM*CDIM];
__device__ __half g_f1h[HIDD*CDIM];
__device__ __half g_f2h[CDIM*HIDD];

// =============================== convert f32 -> f16 ===============================
__global__ void f2h_kernel(const float* __restrict__ src, __half* __restrict__ dst)
{
    int i = blockIdx.x * 256 + threadIdx.x;
    float4 v = ((const float4*)src)[i];
    ((__half2*)dst)[2*i]   = __floats2half2_rn(v.x, v.y);
    ((__half2*)dst)[2*i+1] = __floats2half2_rn(v.z, v.w);
}

// =============================== LayerNorm ===============================
// WRITE_F32 / WRITE_H16 control outputs
template<bool WF, bool WH>
__global__ void ln_kernel(const float* __restrict__ x, const float* __restrict__ w,
                          const float* __restrict__ b, float* __restrict__ out,
                          __half* __restrict__ outh)
{
    int row = blockIdx.x;
    int t   = threadIdx.x;         // 128
    const float* xr = x + row * CDIM;
    float v0 = xr[t], v1 = xr[t + 128], v2 = xr[t + 256];
    float s  = v0 + v1 + v2;
    float sq = v0*v0 + v1*v1 + v2*v2;
    __shared__ float sh[8];
    #pragma unroll
    for (int o = 16; o; o >>= 1) {
        s  += __shfl_down_sync(0xffffffffu, s,  o);
        sq += __shfl_down_sync(0xffffffffu, sq, o);
    }
    if ((t & 31) == 0) { sh[t >> 5] = s; sh[4 + (t >> 5)] = sq; }
    __syncthreads();
    __shared__ float s_mu, s_rstd;
    if (t == 0) {
        float S = sh[0] + sh[1] + sh[2] + sh[3];
        float SQ = sh[4] + sh[5] + sh[6] + sh[7];
        float mu = S / CDIM;
        s_mu = mu;
        s_rstd = rsqrtf(SQ / CDIM - mu * mu + EPSLN);
    }
    __syncthreads();
    float mu = s_mu, rstd = s_rstd;
    float r0 = (v0 - mu) * rstd * w[t]       + b[t];
    float r1 = (v1 - mu) * rstd * w[t + 128] + b[t + 128];
    float r2 = (v2 - mu) * rstd * w[t + 256] + b[t + 256];
    if (WF) {
        float* orow = out + row * CDIM;
        orow[t] = r0; orow[t + 128] = r1; orow[t + 256] = r2;
    }
    if (WH) {
        __half* hrow = outh + row * CDIM;
        hrow[t] = __float2half(r0); hrow[t + 128] = __float2half(r1); hrow[t + 256] = __float2half(r2);
    }
}

// =============================== WMMA GEMM ===============================
// C[M,N] = A[M,K](half) @ W[N,K](half)^T + bias; fp32 accum.
// EPI: 0=none 1=gelu 2=+res; TRANSOUT -> (B,C,ns) f32; OUTH -> half output
template<int EPI, bool TRANSOUT, bool OUTH>
__global__ void hgemm_kernel(const __half* __restrict__ A, const __half* __restrict__ W,
                             const float* __restrict__ bias, const float* __restrict__ res,
                             void* __restrict__ outv, int M, int N, int K)
{
    __shared__ __half As[64][40];
    __shared__ __half Bs[64][40];
    __shared__ float  Cs[64][64];
    int tid = threadIdx.x;               // 128
    int m0 = blockIdx.y * 64, n0 = blockIdx.x * 64;
    int warp = tid >> 5;
    int wy = warp >> 1, wx = warp & 1;   // 2x2 warps, each 32x32

    wmma::fragment<wmma::accumulator, 16,16,16, float> acc[2][2];
    #pragma unroll
    for (int i = 0; i < 2; i++)
        #pragma unroll
        for (int j = 0; j < 2; j++)
            wmma::fill_fragment(acc[i][j], 0.0f);

    for (int k0 = 0; k0 < K; k0 += 32) {
        #pragma unroll
        for (int j = 0; j < 2; j++) {
            int idx = tid + j * 128;
            int r = idx >> 2, c = (idx & 3) * 8;
            *(uint4*)&As[r][c] = *(const uint4*)&A[(size_t)(m0 + r) * K + k0 + c];
            *(uint4*)&Bs[r][c] = *(const uint4*)&W[(size_t)(n0 + r) * K + k0 + c];
        }
        __syncthreads();
        #pragma unroll
        for (int kk = 0; kk < 32; kk += 16) {
            wmma::fragment<wmma::matrix_a, 16,16,16, __half, wmma::row_major> a0, a1;
            wmma::fragment<wmma::matrix_b, 16,16,16, __half, wmma::col_major> b0, b1;
            wmma::load_matrix_sync(a0, &As[wy * 32][kk], 40);
            wmma::load_matrix_sync(a1, &As[wy * 32 + 16][kk], 40);
            wmma::load_matrix_sync(b0, &Bs[wx * 32][kk], 40);
            wmma::load_matrix_sync(b1, &Bs[wx * 32 + 16][kk], 40);
            wmma::mma_sync(acc[0][0], a0, b0, acc[0][0]);
            wmma::mma_sync(acc[0][1], a0, b1, acc[0][1]);
            wmma::mma_sync(acc[1][0], a1, b0, acc[1][0]);
            wmma::mma_sync(acc[1][1], a1, b1, acc[1][1]);
        }
        __syncthreads();
    }
    #pragma unroll
    for (int i = 0; i < 2; i++)
        #pragma unroll
        for (int j = 0; j < 2; j++)
            wmma::store_matrix_sync(&Cs[wy * 32 + i * 16][wx * 32 + j * 16], acc[i][j], 64, wmma::mem_row_major);
    __syncthreads();

    for (int idx = tid; idx < 4096; idx += 128) {
        int mi = idx >> 6, ni = idx & 63;
        int m = m0 + mi, n = n0 + ni;
        float c = Cs[mi][ni] + bias[n];
        if (EPI == 1) c = 0.5f * c * (1.0f + erff(c * 0.70710678118654752f));
        if (EPI == 2) c += res[(size_t)m * N + n];
        if (OUTH) {
            ((__half*)outv)[(size_t)m * N + n] = __float2half(c);
        } else if (TRANSOUT) {
            ((float*)outv)[(size_t)(m >> 10) * N * 1024 + (size_t)n * 1024 + (m & 1023)] = c;
        } else {
            ((float*)outv)[(size_t)m * N + n] = c;
        }
    }
}

// ========================= Offset network (fused) =========================
__global__ void offset_kernel(const float* __restrict__ q, const float* __restrict__ dww,
                              const float* __restrict__ dwb, const float* __restrict__ lnw,
                              const float* __restrict__ lnb, const float* __restrict__ pww,
                              float* __restrict__ pos)
{
    int pix = blockIdx.x;
    int c = threadIdx.x;               // 64
    int bg = pix >> 10;
    int l  = pix & 1023;
    int y = l >> 5, x = l & 31;
    int b = bg / NGRP, g = bg % NGRP;
    int ch = g * CGRP + c;
    const float* w = dww + c * 49;
    float acc = dwb[c];
    #pragma unroll
    for (int dy = -3; dy <= 3; ++dy) {
        int yy = y + dy;
        if ((unsigned)yy >= 32u) continue;
        #pragma unroll
        for (int dx = -3; dx <= 3; ++dx) {
            int xx = x + dx;
            if ((unsigned)xx >= 32u) continue;
            acc += q[(size_t)(b * LDIM + yy * 32 + xx) * CDIM + ch] * w[(dy + 3) * 7 + (dx + 3)];
        }
    }
    float s = acc, sq = acc * acc;
    #pragma unroll
    for (int o = 16; o; o >>= 1) {
        s  += __shfl_down_sync(0xffffffffu, s,  o);
        sq += __shfl_down_sync(0xffffffffu, sq, o);
    }
    __shared__ float sh[4];
    if ((c & 31) == 0) { sh[c >> 5] = s; sh[2 + (c >> 5)] = sq; }
    __syncthreads();
    float mu  = (sh[0] + sh[1]) * (1.0f / 64.0f);
    float var = (sh[2] + sh[3]) * (1.0f / 64.0f) - mu * mu;
    float r = rsqrtf(var + EPSLN);
    float o_ = (acc - mu) * r * lnw[c] + lnb[c];
    o_ = 0.5f * o_ * (1.0f + erff(o_ * 0.70710678118654752f));
    float p0 = o_ * pww[c];
    float p1 = o_ * pww[64 + c];
    #pragma unroll
    for (int o = 16; o; o >>= 1) {
        p0 += __shfl_down_sync(0xffffffffu, p0, o);
        p1 += __shfl_down_sync(0xffffffffu, p1, o);
    }
    __shared__ float ph[4];
    if ((c & 31) == 0) { ph[c >> 5] = p0; ph[2 + (c >> 5)] = p1; }
    __syncthreads();
    if (c == 0) {
        float P0 = ph[0] + ph[1];
        float P1 = ph[2] + ph[3];
        float oy = tanhf(P0) * (2.0f / 32.0f);
        float ox = tanhf(P1) * (2.0f / 32.0f);
        float py = oy + ((y + 0.5f) / 32.0f) * 2.0f - 1.0f;
        float px = ox + ((x + 0.5f) / 32.0f) * 2.0f - 1.0f;
        pos[(size_t)bg * 2048 + l * 2 + 0] = py;
        pos[(size_t)bg * 2048 + l * 2 + 1] = px;
    }
}

// ===================== Deformable bilinear sampling (half out) =====================
__global__ void sample_kernel(const float* __restrict__ xn, const float* __restrict__ pos,
                              __half* __restrict__ xs)
{
    int bn = blockIdx.x;
    int c = threadIdx.x;               // 384
    int b = bn >> 10;
    int n = bn & 1023;
    int g = c >> 6;
    float py = pos[(size_t)(b * NGRP + g) * 2048 + n * 2 + 0];
    float px = pos[(size_t)(b * NGRP + g) * 2048 + n * 2 + 1];
    float fx = (px + 1.0f) * 0.5f * 31.0f;
    float fy = (py + 1.0f) * 0.5f * 31.0f;
    float x0f = floorf(fx), y0f = floorf(fy);
    int x0 = (int)x0f, y0 = (int)y0f;
    float wx = fx - x0f, wy = fy - y0f;
    const float* base = xn + (size_t)b * LDIM * CDIM + c;
    float v = 0.0f;
    if ((unsigned)x0 < 32u && (unsigned)y0 < 32u)
        v += (1 - wx) * (1 - wy) * base[(size_t)(y0 * 32 + x0) * CDIM];
    if ((unsigned)(x0 + 1) < 32u && (unsigned)y0 < 32u)
        v += wx * (1 - wy) * base[(size_t)(y0 * 32 + x0 + 1) * CDIM];
    if ((unsigned)x0 < 32u && (unsigned)(y0 + 1) < 32u)
        v += (1 - wx) * wy * base[(size_t)((y0 + 1) * 32 + x0) * CDIM];
    if ((unsigned)(x0 + 1) < 32u && (unsigned)(y0 + 1) < 32u)
        v += wx * wy * base[(size_t)((y0 + 1) * 32 + x0 + 1) * CDIM];
    xs[(size_t)bn * CDIM + c] = __float2half(v);
}

// ========== Tiled attention v3 (half ao out) ==========
#define ATH 512
#define VPAD 34
#define ATTN_SMEM_FLOATS (32768 + 2048 + 1024 + 128*VPAD + 3972)
__device__ __forceinline__ float rpe_bilin(const float* __restrict__ s_rpe,
                                           float qgy, float qgx, float py, float px)
{
    float fy = ((qgy - py) * 0.5f + 1.0f) * 31.0f;
    float fx = ((qgx - px) * 0.5f + 1.0f) * 31.0f;
    float x0f = floorf(fx), y0f = floorf(fy);
    int xi = (int)x0f, yi = (int)y0f;
    float wx = fx - x0f, wy = fy - y0f;
    float bias = 0.0f;
    if ((unsigned)xi < 63u && (unsigned)yi < 63u)             bias += (1 - wx) * (1 - wy) * s_rpe[yi * 63 + xi];
    if ((unsigned)(xi + 1) < 63u && (unsigned)yi < 63u)       bias += wx * (1 - wy) * s_rpe[yi * 63 + xi + 1];
    if ((unsigned)xi < 63u && (unsigned)(yi + 1) < 63u)       bias += (1 - wx) * wy * s_rpe[(yi + 1) * 63 + xi];
    if ((unsigned)(xi + 1) < 63u && (unsigned)(yi + 1) < 63u) bias += wx * wy * s_rpe[(yi + 1) * 63 + xi + 1];
    return bias;
}

__global__ void attn3_kernel(const float* __restrict__ q, const float* __restrict__ kt,
                             const float* __restrict__ vt, const float* __restrict__ pos,
                             const float* __restrict__ rpe, __half* __restrict__ ao)
{
    extern __shared__ float sm[];
    float* s_logit = sm;                       // 32 x 1024
    float* s_pos   = sm + 32768;               // 2048
    float* s_q     = s_pos + 2048;             // [d][32q]
    float* s_kv    = s_q + 1024;               // K: [d][64n] / V: [n][VPAD]
    float* s_rpe   = s_kv + 128 * VPAD;        // 3969 (+pad)

    int m0 = blockIdx.x * 32;
    int hh = blockIdx.y;
    int b  = blockIdx.z;
    int g  = hh >> 1;
    int t  = threadIdx.x;
    int warp = t >> 5, lane = t & 31;

    const float* posb = pos + (size_t)(b * NGRP + g) * 2048;
    for (int i = t; i < 3969; i += ATH) s_rpe[i] = rpe[hh * 3969 + i];
    for (int i = t; i < 2048; i += ATH) s_pos[i] = posb[i];
    for (int i = t; i < 1024; i += ATH) {
        int qq = i >> 5, d = i & 31;
        s_q[d * 32 + qq] = q[(size_t)(b * LDIM + m0 + qq) * CDIM + hh * HCH + d];
    }

    int q0 = 2 * warp, q1 = q0 + 1;
    int mg0 = m0 + q0, mg1 = m0 + q1;
    float qgy0 = ((float)(mg0 >> 5) + 0.5f) * (1.0f / 16.0f) - 1.0f;
    float qgx0 = ((float)(mg0 & 31) + 0.5f) * (1.0f / 16.0f) - 1.0f;
    float qgy1 = ((float)(mg1 >> 5) + 0.5f) * (1.0f / 16.0f) - 1.0f;
    float qgx1 = ((float)(mg1 & 31) + 0.5f) * (1.0f / 16.0f) - 1.0f;

    const float* ktb = kt + ((size_t)b * CDIM + hh * HCH) * (size_t)NSD;
    const float scale = 0.17677669529663687f;
    float mrun0 = -1e30f, mrun1 = -1e30f;

    for (int nc = 0; nc < 1024; nc += 64) {
        __syncthreads();
        #pragma unroll
        for (int i = t; i < 2048; i += ATH)
            s_kv[i] = ktb[(size_t)(i >> 6) * NSD + nc + (i & 63)];
        __syncthreads();

        float a00 = 0.f, a01 = 0.f, a10 = 0.f, a11 = 0.f;
        #pragma unroll
        for (int d = 0; d < 32; d++) {
            float2 k2 = *(const float2*)&s_kv[d * 64 + 2 * lane];
            float qa = s_q[d * 32 + q0];
            float qb = s_q[d * 32 + q1];
            a00 += qa * k2.x; a01 += qa * k2.y;
            a10 += qb * k2.x; a11 += qb * k2.y;
        }
        int n0 = nc + 2 * lane;
        float py0 = s_pos[2 * n0],     px0 = s_pos[2 * n0 + 1];
        float py1 = s_pos[2 * n0 + 2], px1 = s_pos[2 * n0 + 3];
        float v00 = a00 * scale + rpe_bilin(s_rpe, qgy0, qgx0, py0, px0);
        float v01 = a01 * scale + rpe_bilin(s_rpe, qgy0, qgx0, py1, px1);
        float v10 = a10 * scale + rpe_bilin(s_rpe, qgy1, qgx1, py0, px0);
        float v11 = a11 * scale + rpe_bilin(s_rpe, qgy1, qgx1, py1, px1);
        *(float2*)&s_logit[q0 * 1024 + n0] = make_float2(v00, v01);
        *(float2*)&s_logit[q1 * 1024 + n0] = make_float2(v10, v11);
        mrun0 = fmaxf(mrun0, fmaxf(v00, v01));
        mrun1 = fmaxf(mrun1, fmaxf(v10, v11));
    }
    #pragma unroll
    for (int o = 16; o; o >>= 1) {
        mrun0 = fmaxf(mrun0, __shfl_xor_sync(0xffffffffu, mrun0, o));
        mrun1 = fmaxf(mrun1, __shfl_xor_sync(0xffffffffu, mrun1, o));
    }
    __syncwarp();

    float* L0 = s_logit + q0 * 1024;
    float* L1 = s_logit + q1 * 1024;
    float sum0 = 0.f, sum1 = 0.f;
    #pragma unroll
    for (int k = 0; k < 8; k++) {
        float4 p = *(float4*)&L0[lane * 4 + k * 128];
        p.x = __expf(p.x - mrun0); p.y = __expf(p.y - mrun0);
        p.z = __expf(p.z - mrun0); p.w = __expf(p.w - mrun0);
        sum0 += p.x + p.y + p.z + p.w;
        *(float4*)&L0[lane * 4 + k * 128] = p;
        float4 r = *(float4*)&L1[lane * 4 + k * 128];
        r.x = __expf(r.x - mrun1); r.y = __expf(r.y - mrun1);
        r.z = __expf(r.z - mrun1); r.w = __expf(r.w - mrun1);
        sum1 += r.x + r.y + r.z + r.w;
        *(float4*)&L1[lane * 4 + k * 128] = r;
    }
    #pragma unroll
    for (int o = 16; o; o >>= 1) {
        sum0 += __shfl_xor_sync(0xffffffffu, sum0, o);
        sum1 += __shfl_xor_sync(0xffffffffu, sum1, o);
    }
    float rinv0 = 1.0f / sum0;
    float rinv1 = 1.0f / sum1;
    __syncwarp();

    const float* vtb = vt + ((size_t)b * CDIM + hh * HCH) * (size_t)NSD;
    int qq = (lane < 16) ? q0 : q1;
    int d0 = 2 * (lane & 15);
    float accA = 0.f, accB = 0.f;

    for (int nc = 0; nc < 1024; nc += 128) {
        __syncthreads();
        #pragma unroll
        for (int i = t; i < 4096; i += ATH) {
            int d = i >> 7, n = i & 127;
            s_kv[n * VPAD + d] = vtb[(size_t)d * NSD + nc + n];
        }
        __syncthreads();
        const float* Lr = s_logit + qq * 1024 + nc;
        #pragma unroll 8
        for (int n = 0; n < 128; n += 4) {
            float4 p4 = *(const float4*)&Lr[n];
            float2 va = *(const float2*)&s_kv[(n + 0) * VPAD + d0];
            float2 vb = *(const float2*)&s_kv[(n + 1) * VPAD + d0];
            float2 vc = *(const float2*)&s_kv[(n + 2) * VPAD + d0];
            float2 vd = *(const float2*)&s_kv[(n + 3) * VPAD + d0];
            accA += p4.x * va.x + p4.y * vb.x + p4.z * vc.x + p4.w * vd.x;
            accB += p4.x * va.y + p4.y * vb.y + p4.z * vc.y + p4.w * vd.y;
        }
    }
    float rinv = (lane < 16) ? rinv0 : rinv1;
    __half2 o2 = __floats2half2_rn(accA * rinv, accB * rinv);
    *(__half2*)&ao[(size_t)(b * LDIM + m0 + qq) * CDIM + hh * HCH + d0] = o2;
}

// =============================== host ===============================
extern "C" void kernel_launch(void* const* d_in, const int* in_sizes, int n_in,
                              void* d_out, int out_size)
{
    const float* x     = (const float*)d_in[0];
    const float* n1w   = (const float*)d_in[1];
    const float* n1b   = (const float*)d_in[2];
    const float* wq    = (const float*)d_in[3];
    const float* bq    = (const float*)d_in[4];
    const float* wk    = (const float*)d_in[5];
    const float* bk    = (const float*)d_in[6];
    const float* wv    = (const float*)d_in[7];
    const float* bv    = (const float*)d_in[8];
    const float* wo    = (const float*)d_in[9];
    const float* bo    = (const float*)d_in[10];
    const float* dww   = (const float*)d_in[11];
    const float* dwb   = (const float*)d_in[12];
    const float* lnw   = (const float*)d_in[13];
    const float* lnb   = (const float*)d_in[14];
    const float* pww   = (const float*)d_in[15];
    const float* rpe   = (const float*)d_in[16];
    const float* n2w   = (const float*)d_in[17];
    const float* n2b   = (const float*)d_in[18];
    const float* fc1w  = (const float*)d_in[19];
    const float* fc1b  = (const float*)d_in[20];
    const float* fc2w  = (const float*)d_in[21];
    const float* fc2b  = (const float*)d_in[22];
    float* out = (float*)d_out;

    float *p_xn, *p_q, *p_pos, *p_kt, *p_vt, *p_x2;
    __half *p_xnh, *p_xsh, *p_aoh, *p_ln2h, *p_h1h;
    __half *p_wqh, *p_wkh, *p_wvh, *p_woh, *p_f1h, *p_f2h;
    cudaGetSymbolAddress((void**)&p_xn,  g_xn);
    cudaGetSymbolAddress((void**)&p_xnh, g_xnh);
    cudaGetSymbolAddress((void**)&p_q,   g_q);
    cudaGetSymbolAddress((void**)&p_pos, g_pos);
    cudaGetSymbolAddress((void**)&p_xsh, g_xsh);
    cudaGetSymbolAddress((void**)&p_kt,  g_kt);
    cudaGetSymbolAddress((void**)&p_vt,  g_vt);
    cudaGetSymbolAddress((void**)&p_aoh, g_aoh);
    cudaGetSymbolAddress((void**)&p_x2,  g_x2);
    cudaGetSymbolAddress((void**)&p_ln2h, g_ln2h);
    cudaGetSymbolAddress((void**)&p_h1h, g_h1h);
    cudaGetSymbolAddress((void**)&p_wqh, g_wqh);
    cudaGetSymbolAddress((void**)&p_wkh, g_wkh);
    cudaGetSymbolAddress((void**)&p_wvh, g_wvh);
    cudaGetSymbolAddress((void**)&p_woh, g_woh);
    cudaGetSymbolAddress((void**)&p_f1h, g_f1h);
    cudaGetSymbolAddress((void**)&p_f2h, g_f2h);

    const int M = BX * LDIM;   // 2048
    const int attn_smem = ATTN_SMEM_FLOATS * (int)sizeof(float);
    cudaFuncSetAttribute(attn3_kernel, cudaFuncAttributeMaxDynamicSharedMemorySize, attn_smem);

    // weight conversions (147456 = 144*1024 ; 589824 = 576*1024)
    f2h_kernel<<<144, 256>>>(wq, p_wqh);
    f2h_kernel<<<144, 256>>>(wk, p_wkh);
    f2h_kernel<<<144, 256>>>(wv, p_wvh);
    f2h_kernel<<<144, 256>>>(wo, p_woh);
    f2h_kernel<<<576, 256>>>(fc1w, p_f1h);
    f2h_kernel<<<576, 256>>>(fc2w, p_f2h);

    // LN1 -> xn (f32) + xn_h
    ln_kernel<true, true><<<M, 128>>>(x, n1w, n1b, p_xn, p_xnh);
    // q projection (f32 out)
    hgemm_kernel<0, false, false><<<dim3(CDIM/64, M/64), 128>>>(p_xnh, p_wqh, bq, nullptr, p_q, M, CDIM, CDIM);
    // offset network -> pos
    offset_kernel<<<BX * NGRP * 1024, 64>>>(p_q, dww, dwb, lnw, lnb, pww, p_pos);
    // deformable sampling -> xs_h
    sample_kernel<<<BX * NSD, CDIM>>>(p_xn, p_pos, p_xsh);
    // k, v projections (TRANSOUT f32)
    hgemm_kernel<0, true, false><<<dim3(CDIM/64, M/64), 128>>>(p_xsh, p_wkh, bk, nullptr, p_kt, M, CDIM, CDIM);
    hgemm_kernel<0, true, false><<<dim3(CDIM/64, M/64), 128>>>(p_xsh, p_wvh, bv, nullptr, p_vt, M, CDIM, CDIM);
    // fused attention -> ao_h
    attn3_kernel<<<dim3(32, NHD, BX), ATH, attn_smem>>>(p_q, p_kt, p_vt, p_pos, rpe, p_aoh);
    // output projection + residual -> x2 (f32)
    hgemm_kernel<2, false, false><<<dim3(CDIM/64, M/64), 128>>>(p_aoh, p_woh, bo, x, p_x2, M, CDIM, CDIM);
    // LN2 -> ln2_h
    ln_kernel<false, true><<<M, 128>>>(p_x2, n2w, n2b, nullptr, p_ln2h);
    // fc1 + gelu -> h1_h
    hgemm_kernel<1, false, true><<<dim3(HIDD/64, M/64), 128>>>(p_ln2h, p_f1h, fc1b, nullptr, p_h1h, M, HIDD, CDIM);
    // fc2 + residual -> out (f32)
    hgemm_kernel<2, false, false><<<dim3(CDIM/64, M/64), 128>>>(p_h1h, p_f2h, fc2b, p_x2, out, M, CDIM, HIDD);
}

// round 6
// speedup vs baseline: 2.9278x; 1.6002x over previous
#include <cuda_runtime.h>
#include <cuda_fp16.h>
#include <mma.h>
#include <math.h>
using namespace nvcuda;

// ---- problem constants ----
#define BX   2
#define CDIM 384
#define NHD  12
#define NGRP 6
#define CGRP 64
#define HCH  32
#define LDIM 1024
#define NSD  1024
#define HIDD 1536
#define EPSLN 1e-5f

// ---- scratch ----
__device__ float  g_xn [BX*LDIM*CDIM];
__device__ __half g_xnh[BX*LDIM*CDIM];
__device__ float  g_q  [BX*LDIM*CDIM];
__device__ float  g_pos[BX*NGRP*NSD*2];
__device__ __half g_xsh[BX*NSD*CDIM];
__device__ __half g_kth[BX*CDIM*NSD];
__device__ __half g_vth[BX*CDIM*NSD];
__device__ __half g_aoh[BX*LDIM*CDIM];
__device__ float  g_x2 [BX*LDIM*CDIM];
__device__ __half g_ln2h[BX*LDIM*CDIM];
__device__ __half g_h1h[BX*LDIM*HIDD];
// half weights
__device__ __half g_wqh[CDIM*CDIM];
__device__ __half g_wkh[CDIM*CDIM];
__device__ __half g_wvh[CDIM*CDIM];
__device__ __half g_woh[CDIM*CDIM];
__device__ __half g_f1h[HIDD*CDIM];
__device__ __half g_f2h[CDIM*HIDD];

// =============================== convert f32 -> f16 ===============================
__global__ void f2h_kernel(const float* __restrict__ src, __half* __restrict__ dst)
{
    int i = blockIdx.x * 256 + threadIdx.x;
    float4 v = ((const float4*)src)[i];
    ((__half2*)dst)[2*i]   = __floats2half2_rn(v.x, v.y);
    ((__half2*)dst)[2*i+1] = __floats2half2_rn(v.z, v.w);
}

// =============================== LayerNorm ===============================
template<bool WF, bool WH>
__global__ void ln_kernel(const float* __restrict__ x, const float* __restrict__ w,
                          const float* __restrict__ b, float* __restrict__ out,
                          __half* __restrict__ outh)
{
    int row = blockIdx.x;
    int t   = threadIdx.x;         // 128
    const float* xr = x + row * CDIM;
    float v0 = xr[t], v1 = xr[t + 128], v2 = xr[t + 256];
    float s  = v0 + v1 + v2;
    float sq = v0*v0 + v1*v1 + v2*v2;
    __shared__ float sh[8];
    #pragma unroll
    for (int o = 16; o; o >>= 1) {
        s  += __shfl_down_sync(0xffffffffu, s,  o);
        sq += __shfl_down_sync(0xffffffffu, sq, o);
    }
    if ((t & 31) == 0) { sh[t >> 5] = s; sh[4 + (t >> 5)] = sq; }
    __syncthreads();
    __shared__ float s_mu, s_rstd;
    if (t == 0) {
        float S = sh[0] + sh[1] + sh[2] + sh[3];
        float SQ = sh[4] + sh[5] + sh[6] + sh[7];
        float mu = S / CDIM;
        s_mu = mu;
        s_rstd = rsqrtf(SQ / CDIM - mu * mu + EPSLN);
    }
    __syncthreads();
    float mu = s_mu, rstd = s_rstd;
    float r0 = (v0 - mu) * rstd * w[t]       + b[t];
    float r1 = (v1 - mu) * rstd * w[t + 128] + b[t + 128];
    float r2 = (v2 - mu) * rstd * w[t + 256] + b[t + 256];
    if (WF) {
        float* orow = out + row * CDIM;
        orow[t] = r0; orow[t + 128] = r1; orow[t + 256] = r2;
    }
    if (WH) {
        __half* hrow = outh + row * CDIM;
        hrow[t] = __float2half(r0); hrow[t + 128] = __float2half(r1); hrow[t + 256] = __float2half(r2);
    }
}

// =============================== WMMA GEMM ===============================
// C[M,N] = A[M,K](half) @ W[N,K](half)^T + bias; fp32 accum.
// EPI: 0=none 1=gelu 2=+res; TRANSOUT -> (B,C,ns); OUTH -> half output
template<int EPI, bool TRANSOUT, bool OUTH>
__global__ void hgemm_kernel(const __half* __restrict__ A, const __half* __restrict__ W,
                             const float* __restrict__ bias, const float* __restrict__ res,
                             void* __restrict__ outv, int M, int N, int K)
{
    __shared__ __half As[64][40];
    __shared__ __half Bs[64][40];
    __shared__ float  Cs[64][64];
    int tid = threadIdx.x;               // 128
    int m0 = blockIdx.y * 64, n0 = blockIdx.x * 64;
    int warp = tid >> 5;
    int wy = warp >> 1, wx = warp & 1;

    wmma::fragment<wmma::accumulator, 16,16,16, float> acc[2][2];
    #pragma unroll
    for (int i = 0; i < 2; i++)
        #pragma unroll
        for (int j = 0; j < 2; j++)
            wmma::fill_fragment(acc[i][j], 0.0f);

    for (int k0 = 0; k0 < K; k0 += 32) {
        #pragma unroll
        for (int j = 0; j < 2; j++) {
            int idx = tid + j * 128;
            int r = idx >> 2, c = (idx & 3) * 8;
            *(uint4*)&As[r][c] = *(const uint4*)&A[(size_t)(m0 + r) * K + k0 + c];
            *(uint4*)&Bs[r][c] = *(const uint4*)&W[(size_t)(n0 + r) * K + k0 + c];
        }
        __syncthreads();
        #pragma unroll
        for (int kk = 0; kk < 32; kk += 16) {
            wmma::fragment<wmma::matrix_a, 16,16,16, __half, wmma::row_major> a0, a1;
            wmma::fragment<wmma::matrix_b, 16,16,16, __half, wmma::col_major> b0, b1;
            wmma::load_matrix_sync(a0, &As[wy * 32][kk], 40);
            wmma::load_matrix_sync(a1, &As[wy * 32 + 16][kk], 40);
            wmma::load_matrix_sync(b0, &Bs[wx * 32][kk], 40);
            wmma::load_matrix_sync(b1, &Bs[wx * 32 + 16][kk], 40);
            wmma::mma_sync(acc[0][0], a0, b0, acc[0][0]);
            wmma::mma_sync(acc[0][1], a0, b1, acc[0][1]);
            wmma::mma_sync(acc[1][0], a1, b0, acc[1][0]);
            wmma::mma_sync(acc[1][1], a1, b1, acc[1][1]);
        }
        __syncthreads();
    }
    #pragma unroll
    for (int i = 0; i < 2; i++)
        #pragma unroll
        for (int j = 0; j < 2; j++)
            wmma::store_matrix_sync(&Cs[wy * 32 + i * 16][wx * 32 + j * 16], acc[i][j], 64, wmma::mem_row_major);
    __syncthreads();

    for (int idx = tid; idx < 4096; idx += 128) {
        int mi = idx >> 6, ni = idx & 63;
        int m = m0 + mi, n = n0 + ni;
        float c = Cs[mi][ni] + bias[n];
        if (EPI == 1) c = 0.5f * c * (1.0f + erff(c * 0.70710678118654752f));
        if (EPI == 2) c += res[(size_t)m * N + n];
        if (TRANSOUT) {
            size_t oi = (size_t)(m >> 10) * N * 1024 + (size_t)n * 1024 + (m & 1023);
            if (OUTH) ((__half*)outv)[oi] = __float2half(c);
            else      ((float*)outv)[oi] = c;
        } else if (OUTH) {
            ((__half*)outv)[(size_t)m * N + n] = __float2half(c);
        } else {
            ((float*)outv)[(size_t)m * N + n] = c;
        }
    }
}

// ========================= Offset network (fused) =========================
__global__ void offset_kernel(const float* __restrict__ q, const float* __restrict__ dww,
                              const float* __restrict__ dwb, const float* __restrict__ lnw,
                              const float* __restrict__ lnb, const float* __restrict__ pww,
                              float* __restrict__ pos)
{
    int pix = blockIdx.x;
    int c = threadIdx.x;               // 64
    int bg = pix >> 10;
    int l  = pix & 1023;
    int y = l >> 5, x = l & 31;
    int b = bg / NGRP, g = bg % NGRP;
    int ch = g * CGRP + c;
    const float* w = dww + c * 49;
    float acc = dwb[c];
    #pragma unroll
    for (int dy = -3; dy <= 3; ++dy) {
        int yy = y + dy;
        if ((unsigned)yy >= 32u) continue;
        #pragma unroll
        for (int dx = -3; dx <= 3; ++dx) {
            int xx = x + dx;
            if ((unsigned)xx >= 32u) continue;
            acc += q[(size_t)(b * LDIM + yy * 32 + xx) * CDIM + ch] * w[(dy + 3) * 7 + (dx + 3)];
        }
    }
    float s = acc, sq = acc * acc;
    #pragma unroll
    for (int o = 16; o; o >>= 1) {
        s  += __shfl_down_sync(0xffffffffu, s,  o);
        sq += __shfl_down_sync(0xffffffffu, sq, o);
    }
    __shared__ float sh[4];
    if ((c & 31) == 0) { sh[c >> 5] = s; sh[2 + (c >> 5)] = sq; }
    __syncthreads();
    float mu  = (sh[0] + sh[1]) * (1.0f / 64.0f);
    float var = (sh[2] + sh[3]) * (1.0f / 64.0f) - mu * mu;
    float r = rsqrtf(var + EPSLN);
    float o_ = (acc - mu) * r * lnw[c] + lnb[c];
    o_ = 0.5f * o_ * (1.0f + erff(o_ * 0.70710678118654752f));
    float p0 = o_ * pww[c];
    float p1 = o_ * pww[64 + c];
    #pragma unroll
    for (int o = 16; o; o >>= 1) {
        p0 += __shfl_down_sync(0xffffffffu, p0, o);
        p1 += __shfl_down_sync(0xffffffffu, p1, o);
    }
    __shared__ float ph[4];
    if ((c & 31) == 0) { ph[c >> 5] = p0; ph[2 + (c >> 5)] = p1; }
    __syncthreads();
    if (c == 0) {
        float P0 = ph[0] + ph[1];
        float P1 = ph[2] + ph[3];
        float oy = tanhf(P0) * (2.0f / 32.0f);
        float ox = tanhf(P1) * (2.0f / 32.0f);
        float py = oy + ((y + 0.5f) / 32.0f) * 2.0f - 1.0f;
        float px = ox + ((x + 0.5f) / 32.0f) * 2.0f - 1.0f;
        pos[(size_t)bg * 2048 + l * 2 + 0] = py;
        pos[(size_t)bg * 2048 + l * 2 + 1] = px;
    }
}

// ===================== Deformable bilinear sampling (half out) =====================
__global__ void sample_kernel(const float* __restrict__ xn, const float* __restrict__ pos,
                              __half* __restrict__ xs)
{
    int bn = blockIdx.x;
    int c = threadIdx.x;               // 384
    int b = bn >> 10;
    int n = bn & 1023;
    int g = c >> 6;
    float py = pos[(size_t)(b * NGRP + g) * 2048 + n * 2 + 0];
    float px = pos[(size_t)(b * NGRP + g) * 2048 + n * 2 + 1];
    float fx = (px + 1.0f) * 0.5f * 31.0f;
    float fy = (py + 1.0f) * 0.5f * 31.0f;
    float x0f = floorf(fx), y0f = floorf(fy);
    int x0 = (int)x0f, y0 = (int)y0f;
    float wx = fx - x0f, wy = fy - y0f;
    const float* base = xn + (size_t)b * LDIM * CDIM + c;
    float v = 0.0f;
    if ((unsigned)x0 < 32u && (unsigned)y0 < 32u)
        v += (1 - wx) * (1 - wy) * base[(size_t)(y0 * 32 + x0) * CDIM];
    if ((unsigned)(x0 + 1) < 32u && (unsigned)y0 < 32u)
        v += wx * (1 - wy) * base[(size_t)(y0 * 32 + x0 + 1) * CDIM];
    if ((unsigned)x0 < 32u && (unsigned)(y0 + 1) < 32u)
        v += (1 - wx) * wy * base[(size_t)((y0 + 1) * 32 + x0) * CDIM];
    if ((unsigned)(x0 + 1) < 32u && (unsigned)(y0 + 1) < 32u)
        v += wx * wy * base[(size_t)((y0 + 1) * 32 + x0 + 1) * CDIM];
    xs[(size_t)bn * CDIM + c] = __float2half(v);
}

// ========== Attention v4: WMMA QK + SIMT bias/softmax + WMMA AV ==========
#define ATH 512   // 16 warps
// smem floats-equivalent total
#define ATTN_SMEM_BYTES (131072 + 8192 + 15888 + 128 + 65536 + 2560)
__device__ __forceinline__ float rpe_bilin(const float* __restrict__ s_rpe,
                                           float qgy, float qgx, float py, float px)
{
    float fy = ((qgy - py) * 0.5f + 1.0f) * 31.0f;
    float fx = ((qgx - px) * 0.5f + 1.0f) * 31.0f;
    float x0f = floorf(fx), y0f = floorf(fy);
    int xi = (int)x0f, yi = (int)y0f;
    float wx = fx - x0f, wy = fy - y0f;
    float bias = 0.0f;
    if ((unsigned)xi < 63u && (unsigned)yi < 63u)             bias += (1 - wx) * (1 - wy) * s_rpe[yi * 63 + xi];
    if ((unsigned)(xi + 1) < 63u && (unsigned)yi < 63u)       bias += wx * (1 - wy) * s_rpe[yi * 63 + xi + 1];
    if ((unsigned)xi < 63u && (unsigned)(yi + 1) < 63u)       bias += (1 - wx) * wy * s_rpe[(yi + 1) * 63 + xi];
    if ((unsigned)(xi + 1) < 63u && (unsigned)(yi + 1) < 63u) bias += wx * wy * s_rpe[(yi + 1) * 63 + xi + 1];
    return bias;
}

__global__ void attn4_kernel(const float* __restrict__ q, const __half* __restrict__ kt,
                             const __half* __restrict__ vt, const float* __restrict__ pos,
                             const float* __restrict__ rpe, __half* __restrict__ ao)
{
    extern __shared__ float sm[];
    float*  s_logit = sm;                          // 32768 f (also AV reduction scratch)
    float*  s_pos   = sm + 32768;                  // 2048 f
    float*  s_rpe   = s_pos + 2048;                // 3972 f
    float*  s_rinv  = s_rpe + 3972;                // 32 f
    __half* s_p     = (__half*)(s_rinv + 32);      // 32768 h
    __half* s_q     = s_p + 32768;                 // 32 x 40 h

    int m0 = blockIdx.x * 32;
    int hh = blockIdx.y;
    int b  = blockIdx.z;
    int g  = hh >> 1;
    int t  = threadIdx.x;
    int w  = t >> 5, lane = t & 31;

    const float* posb = pos + (size_t)(b * NGRP + g) * 2048;
    for (int i = t; i < 3969; i += ATH) s_rpe[i] = rpe[hh * 3969 + i];
    for (int i = t; i < 2048; i += ATH) s_pos[i] = posb[i];
    for (int i = t; i < 1024; i += ATH) {
        int m = i >> 5, d = i & 31;
        s_q[m * 40 + d] = __float2half(q[(size_t)(b * LDIM + m0 + m) * CDIM + hh * HCH + d]);
    }
    __syncthreads();

    const __half* ktb = kt + ((size_t)b * CDIM + hh * HCH) * (size_t)NSD;
    const __half* vtb = vt + ((size_t)b * CDIM + hh * HCH) * (size_t)NSD;

    // ---- QK: warp w computes rows 0..31 x cols [w*64, w*64+64) ----
    {
        wmma::fragment<wmma::matrix_a, 16,16,16, __half, wmma::row_major> af[2][2];
        #pragma unroll
        for (int mi = 0; mi < 2; mi++)
            #pragma unroll
            for (int ki = 0; ki < 2; ki++)
                wmma::load_matrix_sync(af[mi][ki], &s_q[mi * 16 * 40 + ki * 16], 40);

        #pragma unroll
        for (int nf = 0; nf < 4; nf++) {
            int n = w * 64 + nf * 16;
            wmma::fragment<wmma::matrix_b, 16,16,16, __half, wmma::row_major> bf[2];
            wmma::load_matrix_sync(bf[0], ktb + n, NSD);
            wmma::load_matrix_sync(bf[1], ktb + (size_t)16 * NSD + n, NSD);
            wmma::fragment<wmma::accumulator, 16,16,16, float> acc[2];
            wmma::fill_fragment(acc[0], 0.0f);
            wmma::fill_fragment(acc[1], 0.0f);
            #pragma unroll
            for (int ki = 0; ki < 2; ki++) {
                wmma::mma_sync(acc[0], af[0][ki], bf[ki], acc[0]);
                wmma::mma_sync(acc[1], af[1][ki], bf[ki], acc[1]);
            }
            wmma::store_matrix_sync(&s_logit[0 * 16384 + n], acc[0], 1024, wmma::mem_row_major);
            wmma::store_matrix_sync(&s_logit[1 * 16384 + n], acc[1], 1024, wmma::mem_row_major);
        }
    }
    __syncthreads();

    // ---- bias + max (warp owns rows q0, q1) ----
    int q0 = 2 * w, q1 = q0 + 1;
    int mg0 = m0 + q0, mg1 = m0 + q1;
    float qgy0 = ((float)(mg0 >> 5) + 0.5f) * (1.0f / 16.0f) - 1.0f;
    float qgx0 = ((float)(mg0 & 31) + 0.5f) * (1.0f / 16.0f) - 1.0f;
    float qgy1 = ((float)(mg1 >> 5) + 0.5f) * (1.0f / 16.0f) - 1.0f;
    float qgx1 = ((float)(mg1 & 31) + 0.5f) * (1.0f / 16.0f) - 1.0f;
    const float scale = 0.17677669529663687f;
    float* L0 = s_logit + q0 * 1024;
    float* L1 = s_logit + q1 * 1024;
    float mrun0 = -1e30f, mrun1 = -1e30f;

    #pragma unroll
    for (int k = 0; k < 8; k++) {
        int n4 = lane * 4 + k * 128;
        float4 pA = *(const float4*)&s_pos[2 * n4];       // y0 x0 y1 x1
        float4 pB = *(const float4*)&s_pos[2 * n4 + 4];   // y2 x2 y3 x3
        float4 a = *(float4*)&L0[n4];
        a.x = a.x * scale + rpe_bilin(s_rpe, qgy0, qgx0, pA.x, pA.y);
        a.y = a.y * scale + rpe_bilin(s_rpe, qgy0, qgx0, pA.z, pA.w);
        a.z = a.z * scale + rpe_bilin(s_rpe, qgy0, qgx0, pB.x, pB.y);
        a.w = a.w * scale + rpe_bilin(s_rpe, qgy0, qgx0, pB.z, pB.w);
        *(float4*)&L0[n4] = a;
        mrun0 = fmaxf(mrun0, fmaxf(fmaxf(a.x, a.y), fmaxf(a.z, a.w)));
        float4 c = *(float4*)&L1[n4];
        c.x = c.x * scale + rpe_bilin(s_rpe, qgy1, qgx1, pA.x, pA.y);
        c.y = c.y * scale + rpe_bilin(s_rpe, qgy1, qgx1, pA.z, pA.w);
        c.z = c.z * scale + rpe_bilin(s_rpe, qgy1, qgx1, pB.x, pB.y);
        c.w = c.w * scale + rpe_bilin(s_rpe, qgy1, qgx1, pB.z, pB.w);
        *(float4*)&L1[n4] = c;
        mrun1 = fmaxf(mrun1, fmaxf(fmaxf(c.x, c.y), fmaxf(c.z, c.w)));
    }
    #pragma unroll
    for (int o = 16; o; o >>= 1) {
        mrun0 = fmaxf(mrun0, __shfl_xor_sync(0xffffffffu, mrun0, o));
        mrun1 = fmaxf(mrun1, __shfl_xor_sync(0xffffffffu, mrun1, o));
    }

    // ---- exp (write half P) + sum ----
    float sum0 = 0.f, sum1 = 0.f;
    #pragma unroll
    for (int k = 0; k < 8; k++) {
        int n4 = lane * 4 + k * 128;
        float4 a = *(float4*)&L0[n4];
        a.x = __expf(a.x - mrun0); a.y = __expf(a.y - mrun0);
        a.z = __expf(a.z - mrun0); a.w = __expf(a.w - mrun0);
        sum0 += a.x + a.y + a.z + a.w;
        *(__half2*)&s_p[q0 * 1024 + n4]     = __floats2half2_rn(a.x, a.y);
        *(__half2*)&s_p[q0 * 1024 + n4 + 2] = __floats2half2_rn(a.z, a.w);
        float4 c = *(float4*)&L1[n4];
        c.x = __expf(c.x - mrun1); c.y = __expf(c.y - mrun1);
        c.z = __expf(c.z - mrun1); c.w = __expf(c.w - mrun1);
        sum1 += c.x + c.y + c.z + c.w;
        *(__half2*)&s_p[q1 * 1024 + n4]     = __floats2half2_rn(c.x, c.y);
        *(__half2*)&s_p[q1 * 1024 + n4 + 2] = __floats2half2_rn(c.z, c.w);
    }
    #pragma unroll
    for (int o = 16; o; o >>= 1) {
        sum0 += __shfl_xor_sync(0xffffffffu, sum0, o);
        sum1 += __shfl_xor_sync(0xffffffffu, sum1, o);
    }
    if (lane == 0) { s_rinv[q0] = 1.0f / sum0; s_rinv[q1] = 1.0f / sum1; }
    __syncthreads();

    // ---- AV: split-k over 16 warps (each k-range 64), reduce in s_logit ----
    {
        wmma::fragment<wmma::accumulator, 16,16,16, float> oacc[2][2];
        #pragma unroll
        for (int mi = 0; mi < 2; mi++)
            #pragma unroll
            for (int di = 0; di < 2; di++)
                wmma::fill_fragment(oacc[mi][di], 0.0f);
        #pragma unroll
        for (int kf = 0; kf < 4; kf++) {
            int kk = w * 64 + kf * 16;
            wmma::fragment<wmma::matrix_a, 16,16,16, __half, wmma::row_major> pa[2];
            wmma::load_matrix_sync(pa[0], &s_p[0 * 16384 + kk], 1024);
            wmma::load_matrix_sync(pa[1], &s_p[1 * 16384 + kk], 1024);
            wmma::fragment<wmma::matrix_b, 16,16,16, __half, wmma::col_major> vb[2];
            wmma::load_matrix_sync(vb[0], vtb + kk, NSD);
            wmma::load_matrix_sync(vb[1], vtb + (size_t)16 * NSD + kk, NSD);
            #pragma unroll
            for (int mi = 0; mi < 2; mi++)
                #pragma unroll
                for (int di = 0; di < 2; di++)
                    wmma::mma_sync(oacc[mi][di], pa[mi], vb[di], oacc[mi][di]);
        }
        float* scr = s_logit + w * 1024;
        #pragma unroll
        for (int mi = 0; mi < 2; mi++)
            #pragma unroll
            for (int di = 0; di < 2; di++)
                wmma::store_matrix_sync(&scr[mi * 16 * 32 + di * 16], oacc[mi][di], 32, wmma::mem_row_major);
    }
    __syncthreads();

    #pragma unroll
    for (int idx = t; idx < 1024; idx += ATH) {
        float s = 0.f;
        #pragma unroll
        for (int ww = 0; ww < 16; ww++) s += s_logit[ww * 1024 + idx];
        int m = idx >> 5, d = idx & 31;
        ao[(size_t)(b * LDIM + m0 + m) * CDIM + hh * HCH + d] = __float2half(s * s_rinv[m]);
    }
}

// =============================== host ===============================
extern "C" void kernel_launch(void* const* d_in, const int* in_sizes, int n_in,
                              void* d_out, int out_size)
{
    const float* x     = (const float*)d_in[0];
    const float* n1w   = (const float*)d_in[1];
    const float* n1b   = (const float*)d_in[2];
    const float* wq    = (const float*)d_in[3];
    const float* bq    = (const float*)d_in[4];
    const float* wk    = (const float*)d_in[5];
    const float* bk    = (const float*)d_in[6];
    const float* wv    = (const float*)d_in[7];
    const float* bv    = (const float*)d_in[8];
    const float* wo    = (const float*)d_in[9];
    const float* bo    = (const float*)d_in[10];
    const float* dww   = (const float*)d_in[11];
    const float* dwb   = (const float*)d_in[12];
    const float* lnw   = (const float*)d_in[13];
    const float* lnb   = (const float*)d_in[14];
    const float* pww   = (const float*)d_in[15];
    const float* rpe   = (const float*)d_in[16];
    const float* n2w   = (const float*)d_in[17];
    const float* n2b   = (const float*)d_in[18];
    const float* fc1w  = (const float*)d_in[19];
    const float* fc1b  = (const float*)d_in[20];
    const float* fc2w  = (const float*)d_in[21];
    const float* fc2b  = (const float*)d_in[22];
    float* out = (float*)d_out;

    float *p_xn, *p_q, *p_pos, *p_x2;
    __half *p_xnh, *p_xsh, *p_kth, *p_vth, *p_aoh, *p_ln2h, *p_h1h;
    __half *p_wqh, *p_wkh, *p_wvh, *p_woh, *p_f1h, *p_f2h;
    cudaGetSymbolAddress((void**)&p_xn,  g_xn);
    cudaGetSymbolAddress((void**)&p_xnh, g_xnh);
    cudaGetSymbolAddress((void**)&p_q,   g_q);
    cudaGetSymbolAddress((void**)&p_pos, g_pos);
    cudaGetSymbolAddress((void**)&p_xsh, g_xsh);
    cudaGetSymbolAddress((void**)&p_kth, g_kth);
    cudaGetSymbolAddress((void**)&p_vth, g_vth);
    cudaGetSymbolAddress((void**)&p_aoh, g_aoh);
    cudaGetSymbolAddress((void**)&p_x2,  g_x2);
    cudaGetSymbolAddress((void**)&p_ln2h, g_ln2h);
    cudaGetSymbolAddress((void**)&p_h1h, g_h1h);
    cudaGetSymbolAddress((void**)&p_wqh, g_wqh);
    cudaGetSymbolAddress((void**)&p_wkh, g_wkh);
    cudaGetSymbolAddress((void**)&p_wvh, g_wvh);
    cudaGetSymbolAddress((void**)&p_woh, g_woh);
    cudaGetSymbolAddress((void**)&p_f1h, g_f1h);
    cudaGetSymbolAddress((void**)&p_f2h, g_f2h);

    const int M = BX * LDIM;   // 2048
    cudaFuncSetAttribute(attn4_kernel, cudaFuncAttributeMaxDynamicSharedMemorySize, ATTN_SMEM_BYTES);

    f2h_kernel<<<144, 256>>>(wq, p_wqh);
    f2h_kernel<<<144, 256>>>(wk, p_wkh);
    f2h_kernel<<<144, 256>>>(wv, p_wvh);
    f2h_kernel<<<144, 256>>>(wo, p_woh);
    f2h_kernel<<<576, 256>>>(fc1w, p_f1h);
    f2h_kernel<<<576, 256>>>(fc2w, p_f2h);

    ln_kernel<true, true><<<M, 128>>>(x, n1w, n1b, p_xn, p_xnh);
    hgemm_kernel<0, false, false><<<dim3(CDIM/64, M/64), 128>>>(p_xnh, p_wqh, bq, nullptr, p_q, M, CDIM, CDIM);
    offset_kernel<<<BX * NGRP * 1024, 64>>>(p_q, dww, dwb, lnw, lnb, pww, p_pos);
    sample_kernel<<<BX * NSD, CDIM>>>(p_xn, p_pos, p_xsh);
    hgemm_kernel<0, true, true><<<dim3(CDIM/64, M/64), 128>>>(p_xsh, p_wkh, bk, nullptr, p_kth, M, CDIM, CDIM);
    hgemm_kernel<0, true, true><<<dim3(CDIM/64, M/64), 128>>>(p_xsh, p_wvh, bv, nullptr, p_vth, M, CDIM, CDIM);
    attn4_kernel<<<dim3(32, NHD, BX), ATH, ATTN_SMEM_BYTES>>>(p_q, p_kth, p_vth, p_pos, rpe, p_aoh);
    hgemm_kernel<2, false, false><<<dim3(CDIM/64, M/64), 128>>>(p_aoh, p_woh, bo, x, p_x2, M, CDIM, CDIM);
    ln_kernel<false, true><<<M, 128>>>(p_x2, n2w, n2b, nullptr, p_ln2h);
    hgemm_kernel<1, false, true><<<dim3(HIDD/64, M/64), 128>>>(p_ln2h, p_f1h, fc1b, nullptr, p_h1h, M, HIDD, CDIM);
    hgemm_kernel<2, false, false><<<dim3(CDIM/64, M/64), 128>>>(p_h1h, p_f2h, fc2b, p_x2, out, M, CDIM, HIDD);
}